// round 12
// baseline (speedup 1.0000x reference)
#include <cuda_runtime.h>
#include <cuda_bf16.h>
#include <cfloat>
#include <cstdint>

#define Bsz 8
#define Npt 1024
#define KNN 20
#define CKS 24   // bf16 row stride in smem (48B: conflict-free, 16B-aligned)
#define BUFB (128 * CKS * 2)   // bytes per smem buffer (6144)

// ---------------- scratch (device globals; no allocation) ----------------
__device__ float    g_xx[Bsz * Npt];                     // squared norms
__device__ float    g_dist[(size_t)Bsz * Npt * Npt];     // dist matrix
__device__ int      g_idx[Bsz * Npt * KNN];              // knn indices
__device__ float    g_Y[(size_t)Bsz * Npt * 512];        // per-layer GEMM output (B*N, 2*O)
__device__ float    g_Weff[92160];                       // folded weights fp32 (layer-1 use)
__device__ unsigned g_pool[Bsz * 1024];                  // global max pool (monotonic-uint)
__device__ __nv_bfloat16 g_Fh[(size_t)8192 * 512];       // features hi (x1|x2|x3|x4)
__device__ __nv_bfloat16 g_Fl[(size_t)8192 * 512];       // features lo
__device__ __nv_bfloat16 g_Wh[92160];                    // folded weights hi
__device__ __nv_bfloat16 g_Wl[92160];                    // folded weights lo
__device__ __nv_bfloat16 g_Bh[(size_t)1024 * 512];       // conv5 weight hi
__device__ __nv_bfloat16 g_Bl[(size_t)1024 * 512];       // conv5 weight lo

// Weff segment offsets (2O x C):  L1 128x3, L2 128x64, L3 256x64, L4 512x128
#define WOFF1 0
#define WOFF2 384
#define WOFF3 8576
#define WOFF4 24960
#define WEND  90496

// monotonic float<->uint encoding
__device__ __forceinline__ unsigned fenc(float v) {
    unsigned u = __float_as_uint(v);
    return (u & 0x80000000u) ? ~u : (u | 0x80000000u);
}
__device__ __forceinline__ float fdec(unsigned u) {
    unsigned f = (u & 0x80000000u) ? (u ^ 0x80000000u) : ~u;
    return __uint_as_float(f);
}

// bf16 mma.sync m16n8k16 (legacy tensor path — compiles for compute_103)
__device__ __forceinline__ void mma16816(float (&d)[4], const uint32_t (&a)[4],
                                         const uint32_t (&b)[2]) {
    asm volatile("mma.sync.aligned.m16n8k16.row.col.f32.bf16.bf16.f32 "
                 "{%0,%1,%2,%3}, {%4,%5,%6,%7}, {%8,%9}, {%0,%1,%2,%3};"
                 : "+f"(d[0]), "+f"(d[1]), "+f"(d[2]), "+f"(d[3])
                 : "r"(a[0]), "r"(a[1]), "r"(a[2]), "r"(a[3]), "r"(b[0]), "r"(b[1]));
}

// cp.async helpers (sm_80+ PTX)
__device__ __forceinline__ void cpa16(uint32_t saddr, const void* g) {
    asm volatile("cp.async.cg.shared.global [%0], [%1], 16;" :: "r"(saddr), "l"(g));
}
#define CPA_COMMIT() asm volatile("cp.async.commit_group;")
#define CPA_WAIT0()  asm volatile("cp.async.wait_group 0;")

// ---------------- prep: fold weights (fp32 + hi/lo bf16) + init pool ----------------
__device__ __forceinline__ float weff_val(const float* __restrict__ W, int O, int C, int i) {
    int j = i / C, c = i - j * C;
    if (j < O) return W[(size_t)j * 2 * C + c];
    int jo = j - O;
    return W[(size_t)jo * 2 * C + C + c] - W[(size_t)jo * 2 * C + c];
}
__global__ void prep_kernel(const float* __restrict__ w1, const float* __restrict__ w2,
                            const float* __restrict__ w3, const float* __restrict__ w4) {
    int i = blockIdx.x * 256 + threadIdx.x;
    if (i < Bsz * 1024) g_pool[i] = 0u;
    if (i >= WEND) return;
    float v;
    if (i < WOFF2)      v = weff_val(w1, 64, 3, i - WOFF1);
    else if (i < WOFF3) v = weff_val(w2, 64, 64, i - WOFF2);
    else if (i < WOFF4) v = weff_val(w3, 128, 64, i - WOFF3);
    else                v = weff_val(w4, 256, 128, i - WOFF4);
    g_Weff[i] = v;
    __nv_bfloat16 h = __float2bfloat16(v);
    g_Wh[i] = h;
    g_Wl[i] = __float2bfloat16(v - __bfloat162float(h));
}

__global__ void sqnorm1_kernel(const float* __restrict__ x) {
    int i = blockIdx.x * 256 + threadIdx.x;
    if (i >= Bsz * Npt) return;
    const float* p = x + (size_t)i * 3;
    g_xx[i] = p[0] * p[0] + p[1] * p[1] + p[2] * p[2];
}

// ---------------- layer-1 fp32 GEMM (K=3): DIST(SYRK) and FEAT ----------------
template <bool DIST>
__global__ void __launch_bounds__(256, 2)
gemm128_kernel(const float* __restrict__ Aext, int Boff, int Csel, int ldc, long sC) {
    constexpr int KDIM = 3;
    __shared__ float As[16][132];
    __shared__ float Bs[16][132];

    const int tid = threadIdx.x;
    const int tx = tid & 15, ty = tid >> 4;
    const int z = blockIdx.z;
    const int lda = 3;

    int bx, by;
    if (DIST) {
        int t = blockIdx.x;
        bx = 0;
        while (t >= bx + 1) { t -= bx + 1; bx++; }
        by = t;
    } else {
        bx = blockIdx.x; by = blockIdx.y;
    }
    const int row0 = bx * 128;
    const int col0 = by * 128;

    const float* A = Aext + (size_t)z * (DIST ? 3 * Npt : 0);
    const float* Bt;
    int ldbb;
    if (DIST) { Bt = A; ldbb = lda; }
    else      { Bt = g_Weff + Boff; ldbb = KDIM; }

    float acc[8][8];
#pragma unroll
    for (int i = 0; i < 8; i++)
#pragma unroll
        for (int j = 0; j < 8; j++) acc[i][j] = 0.f;

#pragma unroll
    for (int l = 0; l < 8; l++) {
        int i = tid + l * 256;
        int r = i >> 4, k = i & 15;
        As[k][r] = (k < KDIM) ? A[(size_t)(row0 + r) * lda + k] : 0.f;
        Bs[k][r] = (k < KDIM) ? Bt[(size_t)(col0 + r) * ldbb + k] : 0.f;
    }
    __syncthreads();
#pragma unroll
    for (int k = 0; k < 3; k++) {
        float4 a0 = *(const float4*)&As[k][ty * 4];
        float4 a1 = *(const float4*)&As[k][ty * 4 + 64];
        float4 b0 = *(const float4*)&Bs[k][tx * 4];
        float4 b1 = *(const float4*)&Bs[k][tx * 4 + 64];
        float av[8] = {a0.x, a0.y, a0.z, a0.w, a1.x, a1.y, a1.z, a1.w};
        float bv[8] = {b0.x, b0.y, b0.z, b0.w, b1.x, b1.y, b1.z, b1.w};
#pragma unroll
        for (int i = 0; i < 8; i++)
#pragma unroll
            for (int j = 0; j < 8; j++)
                acc[i][j] = fmaf(av[i], bv[j], acc[i][j]);
    }

    float* Cp = ((Csel == 0) ? g_dist : g_Y) + (size_t)z * sC;

    if (DIST) {
        const float* xx = g_xx + (size_t)z * Npt;
        float xr[8], xc8[8];
#pragma unroll
        for (int i = 0; i < 8; i++) {
            xr[i]  = xx[row0 + (i >> 2) * 64 + ty * 4 + (i & 3)];
            xc8[i] = xx[col0 + (i >> 2) * 64 + tx * 4 + (i & 3)];
        }
#pragma unroll
        for (int i = 0; i < 8; i++) {
            int r = row0 + (i >> 2) * 64 + ty * 4 + (i & 3);
#pragma unroll
            for (int cs = 0; cs < 2; cs++) {
                float4 o;
                o.x = 2.f * acc[i][cs * 4 + 0] - xr[i] - xc8[cs * 4 + 0];
                o.y = 2.f * acc[i][cs * 4 + 1] - xr[i] - xc8[cs * 4 + 1];
                o.z = 2.f * acc[i][cs * 4 + 2] - xr[i] - xc8[cs * 4 + 2];
                o.w = 2.f * acc[i][cs * 4 + 3] - xr[i] - xc8[cs * 4 + 3];
                *(float4*)&Cp[(size_t)r * ldc + col0 + cs * 64 + tx * 4] = o;
            }
        }
        if (bx != by) {
#pragma unroll
            for (int j = 0; j < 8; j++) {
                int c = col0 + (j >> 2) * 64 + tx * 4 + (j & 3);
#pragma unroll
                for (int rs = 0; rs < 2; rs++) {
                    float4 o;
                    o.x = 2.f * acc[rs * 4 + 0][j] - xr[rs * 4 + 0] - xc8[j];
                    o.y = 2.f * acc[rs * 4 + 1][j] - xr[rs * 4 + 1] - xc8[j];
                    o.z = 2.f * acc[rs * 4 + 2][j] - xr[rs * 4 + 2] - xc8[j];
                    o.w = 2.f * acc[rs * 4 + 3][j] - xr[rs * 4 + 3] - xc8[j];
                    *(float4*)&Cp[(size_t)c * ldc + row0 + rs * 64 + ty * 4] = o;
                }
            }
        }
    } else {
#pragma unroll
        for (int i = 0; i < 8; i++) {
            int r = row0 + (i >> 2) * 64 + ty * 4 + (i & 3);
#pragma unroll
            for (int cs = 0; cs < 2; cs++) {
                float4 o;
                o.x = acc[i][cs * 4 + 0];
                o.y = acc[i][cs * 4 + 1];
                o.z = acc[i][cs * 4 + 2];
                o.w = acc[i][cs * 4 + 3];
                *(float4*)&Cp[(size_t)r * ldc + col0 + cs * 64 + tx * 4] = o;
            }
        }
    }
}

// ---------------- unified bf16-split mma GEMM (layers 2-4) ----------------
// cp.async double-buffered, occupancy 2, one __syncthreads per K-chunk.
template <int KCHUNKS, bool DIST>
__global__ void __launch_bounds__(256, 2)
mma_gemm_kernel(int chanoff, int woff, int twoO) {
    __shared__ __nv_bfloat16 sAh[2][128 * CKS];
    __shared__ __nv_bfloat16 sAl[2][128 * CKS];
    __shared__ __nv_bfloat16 sBh[2][128 * CKS];
    __shared__ __nv_bfloat16 sBl[2][128 * CKS];

    const int tid = threadIdx.x;
    const int wid = tid >> 5, lane = tid & 31;
    const int warp_m = wid & 3, warp_n = wid >> 2;
    const int lr = tid >> 1, lkb = (tid & 1) * 8;
    const int grp = lane >> 2, kq = (lane & 3) * 2;
    const int soffB = (lr * CKS + lkb) * 2;   // bytes

    size_t aoff, boff;
    const __nv_bfloat16 *Bh_, *Bl_;
    if (DIST) {
        aoff = (size_t)(blockIdx.z * 1024 + blockIdx.x * 128 + lr) * 512 + chanoff + lkb;
        boff = (size_t)(blockIdx.z * 1024 + blockIdx.y * 128 + lr) * 512 + chanoff + lkb;
        Bh_ = g_Fh; Bl_ = g_Fl;
    } else {
        aoff = (size_t)(blockIdx.x * 128 + lr) * 512 + chanoff + lkb;
        boff = (size_t)(blockIdx.y * 128 + lr) * (KCHUNKS * 16) + lkb;
        Bh_ = g_Wh + woff; Bl_ = g_Wl + woff;
    }

    const uint32_t sah = (uint32_t)__cvta_generic_to_shared(sAh[0]) + soffB;
    const uint32_t sal = (uint32_t)__cvta_generic_to_shared(sAl[0]) + soffB;
    const uint32_t sbh = (uint32_t)__cvta_generic_to_shared(sBh[0]) + soffB;
    const uint32_t sbl = (uint32_t)__cvta_generic_to_shared(sBl[0]) + soffB;

    float acc[2][8][4];
#pragma unroll
    for (int mt = 0; mt < 2; mt++)
#pragma unroll
        for (int nt = 0; nt < 8; nt++)
#pragma unroll
            for (int f = 0; f < 4; f++) acc[mt][nt][f] = 0.f;

    // issue chunk 0 into buf 0
    cpa16(sah, &g_Fh[aoff]);
    cpa16(sal, &g_Fl[aoff]);
    cpa16(sbh, &Bh_[boff]);
    cpa16(sbl, &Bl_[boff]);
    CPA_COMMIT();
    CPA_WAIT0();
    __syncthreads();

#pragma unroll
    for (int ch = 0; ch < KCHUNKS; ch++) {
        const int buf = ch & 1;
        if (ch + 1 < KCHUNKS) {
            const int nb = (ch + 1) & 1;
            const int kk = (ch + 1) * 16;
            cpa16(sah + nb * BUFB, &g_Fh[aoff + kk]);
            cpa16(sal + nb * BUFB, &g_Fl[aoff + kk]);
            cpa16(sbh + nb * BUFB, &Bh_[boff + kk]);
            cpa16(sbl + nb * BUFB, &Bl_[boff + kk]);
            CPA_COMMIT();
        }
        uint32_t ah[2][4], al[2][4], bh[8][2], bl[8][2];
#pragma unroll
        for (int mt = 0; mt < 2; mt++) {
            int r0 = (warp_m * 32 + mt * 16 + grp) * CKS;
            ah[mt][0] = *(const uint32_t*)&sAh[buf][r0 + kq];
            ah[mt][1] = *(const uint32_t*)&sAh[buf][r0 + 8 * CKS + kq];
            ah[mt][2] = *(const uint32_t*)&sAh[buf][r0 + kq + 8];
            ah[mt][3] = *(const uint32_t*)&sAh[buf][r0 + 8 * CKS + kq + 8];
            al[mt][0] = *(const uint32_t*)&sAl[buf][r0 + kq];
            al[mt][1] = *(const uint32_t*)&sAl[buf][r0 + 8 * CKS + kq];
            al[mt][2] = *(const uint32_t*)&sAl[buf][r0 + kq + 8];
            al[mt][3] = *(const uint32_t*)&sAl[buf][r0 + 8 * CKS + kq + 8];
        }
#pragma unroll
        for (int nt = 0; nt < 8; nt++) {
            int n0 = (warp_n * 64 + nt * 8 + grp) * CKS;
            bh[nt][0] = *(const uint32_t*)&sBh[buf][n0 + kq];
            bh[nt][1] = *(const uint32_t*)&sBh[buf][n0 + kq + 8];
            bl[nt][0] = *(const uint32_t*)&sBl[buf][n0 + kq];
            bl[nt][1] = *(const uint32_t*)&sBl[buf][n0 + kq + 8];
        }
#pragma unroll
        for (int mt = 0; mt < 2; mt++)
#pragma unroll
            for (int nt = 0; nt < 8; nt++) {
                mma16816(acc[mt][nt], ah[mt], bh[nt]);
                mma16816(acc[mt][nt], ah[mt], bl[nt]);
                mma16816(acc[mt][nt], al[mt], bh[nt]);
            }
        if (ch + 1 < KCHUNKS) {
            CPA_WAIT0();
            __syncthreads();
        }
    }

    if (DIST) {
        const float* xx = g_xx + (size_t)blockIdx.z * Npt;
        float* Cp = g_dist + (size_t)blockIdx.z * Npt * Npt;
        const int rb = blockIdx.x * 128 + warp_m * 32;
        const int cb = blockIdx.y * 128 + warp_n * 64;
        float xr[2][2];
#pragma unroll
        for (int mt = 0; mt < 2; mt++) {
            xr[mt][0] = xx[rb + mt * 16 + grp];
            xr[mt][1] = xx[rb + mt * 16 + grp + 8];
        }
#pragma unroll
        for (int nt = 0; nt < 8; nt++) {
            int c = cb + nt * 8 + kq;
            float xc0 = xx[c], xc1 = xx[c + 1];
#pragma unroll
            for (int mt = 0; mt < 2; mt++) {
                int r = rb + mt * 16 + grp;
                *(float2*)&Cp[(size_t)r * Npt + c] = make_float2(
                    2.f * acc[mt][nt][0] - xr[mt][0] - xc0,
                    2.f * acc[mt][nt][1] - xr[mt][0] - xc1);
                *(float2*)&Cp[(size_t)(r + 8) * Npt + c] = make_float2(
                    2.f * acc[mt][nt][2] - xr[mt][1] - xc0,
                    2.f * acc[mt][nt][3] - xr[mt][1] - xc1);
            }
        }
    } else {
        const int rb = blockIdx.x * 128 + warp_m * 32;
        const int cb = blockIdx.y * 128 + warp_n * 64;
#pragma unroll
        for (int mt = 0; mt < 2; mt++) {
            int r = rb + mt * 16 + grp;
#pragma unroll
            for (int nt = 0; nt < 8; nt++) {
                int c = cb + nt * 8 + kq;
                *(float2*)&g_Y[(size_t)r * twoO + c] =
                    make_float2(acc[mt][nt][0], acc[mt][nt][1]);
                *(float2*)&g_Y[(size_t)(r + 8) * twoO + c] =
                    make_float2(acc[mt][nt][2], acc[mt][nt][3]);
            }
        }
    }
}

// ------- top-K (K=20): warp/row, REDUX select, per-lane top-2 heads, lazy refill -------
// slot s (0..31) of lane l holds element gi = (s>>2)*128 + l*4 + (s&3)
__global__ void topk_kernel() {
    const int row = (blockIdx.x << 3) + (threadIdx.x >> 5);
    const int lane = threadIdx.x & 31;
    const float4* rp = (const float4*)(g_dist + (size_t)row * Npt) + lane;

    float v[32];
#pragma unroll
    for (int j = 0; j < 8; j++) {
        float4 t = rp[j * 32];
        v[j * 4 + 0] = t.x; v[j * 4 + 1] = t.y;
        v[j * 4 + 2] = t.z; v[j * 4 + 3] = t.w;
    }

    // per-lane top-2 (strict > keeps lowest slot on ties — exact jax order)
    float m1 = -FLT_MAX, m2 = -FLT_MAX;
    int i1 = 0, i2 = 0;
#pragma unroll
    for (int s = 0; s < 32; s++) {
        float val = v[s];
        if (val > m1) { m2 = m1; i2 = i1; m1 = val; i1 = s; }
        else if (val > m2) { m2 = val; i2 = s; }
    }
    unsigned removed = 0u;
    const int lane4 = lane << 2;

    for (int k = 0; k < KNN; k++) {
        unsigned mykey = fenc(m1);
        unsigned wmax = __reduce_max_sync(0xffffffffu, mykey);
        int gi1 = ((i1 >> 2) << 7) | lane4 | (i1 & 3);
        unsigned cand = (mykey == wmax) ? (unsigned)gi1 : 0xFFFFFFFFu;
        unsigned wini = __reduce_min_sync(0xffffffffu, cand);
        if (lane == 0) g_idx[row * KNN + k] = (int)wini;
        if (cand == wini) {                      // this lane owns the winner
            removed |= 1u << i1;
            m1 = m2; i1 = i2;
            m2 = -FLT_MAX; i2 = 0;
            if (m1 == -FLT_MAX) {                // heads exhausted: refill top-2
#pragma unroll
                for (int s = 0; s < 32; s++) {
                    if (!((removed >> s) & 1u)) {
                        float val = v[s];
                        if (val > m1) { m2 = m1; i2 = i1; m1 = val; i1 = s; }
                        else if (val > m2) { m2 = val; i2 = s; }
                    }
                }
            }
        }
    }
}

// ---- gather + bias + bn + lrelu + max over K; emit bf16 hi/lo features + sqnorm ----
__global__ void aggregate_kernel(int O, const float* __restrict__ bias,
                                 const float* __restrict__ bng, const float* __restrict__ bnb,
                                 int outoff) {
    int bn = blockIdx.x;
    int b = bn >> 10;
    int o = threadIdx.x;
    __shared__ int sidx[KNN];
    __shared__ float sp[8];
    if (o < KNN) sidx[o] = g_idx[bn * KNN + o];
    __syncthreads();
    int twoO = 2 * O;
    const float* Yrow = g_Y + (size_t)bn * twoO;
    float ctr = Yrow[O + o];
    if (bias) ctr += bias[o];
    float scale = bng[o] * rsqrtf(1.0f + 1e-5f);
    float shift = bnb[o];
    const float* Yb = g_Y + (size_t)(b << 10) * twoO;
    float m = -FLT_MAX;
#pragma unroll
    for (int k = 0; k < KNN; k++) {
        float v = Yb[(size_t)sidx[k] * twoO + o] + ctr;
        v = fmaf(v, scale, shift);
        v = (v >= 0.f) ? v : 0.01f * v;
        m = fmaxf(m, v);
    }
    __nv_bfloat16 h = __float2bfloat16(m);
    g_Fh[(size_t)bn * 512 + outoff + o] = h;
    g_Fl[(size_t)bn * 512 + outoff + o] = __float2bfloat16(m - __bfloat162float(h));
    float s = m * m;
#pragma unroll
    for (int off = 16; off; off >>= 1) s += __shfl_xor_sync(0xffffffffu, s, off);
    if ((o & 31) == 0) sp[o >> 5] = s;
    __syncthreads();
    if (o == 0) {
        float t = 0.f;
        int nw = O >> 5;
        for (int w = 0; w < nw; w++) t += sp[w];
        g_xx[bn] = t;
    }
}

// ---------------- conv5 weight split ----------------
__global__ void cvtB_kernel(const float* __restrict__ w5) {
    int i = blockIdx.x * 256 + threadIdx.x;          // [0, 1024*512)
    float x = w5[i];
    __nv_bfloat16 h = __float2bfloat16(x);
    g_Bh[i] = h;
    g_Bl[i] = __float2bfloat16(x - __bfloat162float(h));
}

// ------- conv5: bf16-split mma GEMM (K=512), cp.async pipeline, fused max-pool -------
__global__ void __launch_bounds__(256, 2) conv5_mma_kernel() {
    __shared__ __nv_bfloat16 sAh[2][128 * CKS];
    __shared__ __nv_bfloat16 sAl[2][128 * CKS];
    __shared__ __nv_bfloat16 sBh[2][128 * CKS];
    __shared__ __nv_bfloat16 sBl[2][128 * CKS];

    const int tid = threadIdx.x;
    const int wid = tid >> 5, lane = tid & 31;
    const int warp_m = wid & 3, warp_n = wid >> 2;
    const int row0 = blockIdx.x * 128;
    const int col0 = blockIdx.y * 128;
    const int batch = row0 >> 10;

    const int lr = tid >> 1;
    const int lkb = (tid & 1) * 8;
    const size_t aoff = (size_t)(row0 + lr) * 512 + lkb;
    const size_t boff = (size_t)(col0 + lr) * 512 + lkb;
    const int soffB = (lr * CKS + lkb) * 2;

    const uint32_t sah = (uint32_t)__cvta_generic_to_shared(sAh[0]) + soffB;
    const uint32_t sal = (uint32_t)__cvta_generic_to_shared(sAl[0]) + soffB;
    const uint32_t sbh = (uint32_t)__cvta_generic_to_shared(sBh[0]) + soffB;
    const uint32_t sbl = (uint32_t)__cvta_generic_to_shared(sBl[0]) + soffB;

    float acc[2][8][4];
#pragma unroll
    for (int mt = 0; mt < 2; mt++)
#pragma unroll
        for (int nt = 0; nt < 8; nt++)
#pragma unroll
            for (int f = 0; f < 4; f++) acc[mt][nt][f] = 0.f;

    cpa16(sah, &g_Fh[aoff]);
    cpa16(sal, &g_Fl[aoff]);
    cpa16(sbh, &g_Bh[boff]);
    cpa16(sbl, &g_Bl[boff]);
    CPA_COMMIT();
    CPA_WAIT0();
    __syncthreads();

    const int grp = lane >> 2;
    const int kq = (lane & 3) * 2;

    for (int ch = 0; ch < 32; ch++) {
        const int buf = ch & 1;
        if (ch < 31) {
            const int nb = (ch + 1) & 1;
            const int kk = (ch + 1) * 16;
            cpa16(sah + nb * BUFB, &g_Fh[aoff + kk]);
            cpa16(sal + nb * BUFB, &g_Fl[aoff + kk]);
            cpa16(sbh + nb * BUFB, &g_Bh[boff + kk]);
            cpa16(sbl + nb * BUFB, &g_Bl[boff + kk]);
            CPA_COMMIT();
        }
        uint32_t ah[2][4], al[2][4], bh[8][2], bl[8][2];
#pragma unroll
        for (int mt = 0; mt < 2; mt++) {
            int r0 = (warp_m * 32 + mt * 16 + grp) * CKS;
            ah[mt][0] = *(const uint32_t*)&sAh[buf][r0 + kq];
            ah[mt][1] = *(const uint32_t*)&sAh[buf][r0 + 8 * CKS + kq];
            ah[mt][2] = *(const uint32_t*)&sAh[buf][r0 + kq + 8];
            ah[mt][3] = *(const uint32_t*)&sAh[buf][r0 + 8 * CKS + kq + 8];
            al[mt][0] = *(const uint32_t*)&sAl[buf][r0 + kq];
            al[mt][1] = *(const uint32_t*)&sAl[buf][r0 + 8 * CKS + kq];
            al[mt][2] = *(const uint32_t*)&sAl[buf][r0 + kq + 8];
            al[mt][3] = *(const uint32_t*)&sAl[buf][r0 + 8 * CKS + kq + 8];
        }
#pragma unroll
        for (int nt = 0; nt < 8; nt++) {
            int n0 = (warp_n * 64 + nt * 8 + grp) * CKS;
            bh[nt][0] = *(const uint32_t*)&sBh[buf][n0 + kq];
            bh[nt][1] = *(const uint32_t*)&sBh[buf][n0 + kq + 8];
            bl[nt][0] = *(const uint32_t*)&sBl[buf][n0 + kq];
            bl[nt][1] = *(const uint32_t*)&sBl[buf][n0 + kq + 8];
        }
#pragma unroll
        for (int mt = 0; mt < 2; mt++)
#pragma unroll
            for (int nt = 0; nt < 8; nt++) {
                mma16816(acc[mt][nt], ah[mt], bh[nt]);
                mma16816(acc[mt][nt], ah[mt], bl[nt]);
                mma16816(acc[mt][nt], al[mt], bh[nt]);
            }
        if (ch < 31) {
            CPA_WAIT0();
            __syncthreads();
        }
    }

    float cmax[8][2];
#pragma unroll
    for (int nt = 0; nt < 8; nt++) {
        cmax[nt][0] = fmaxf(fmaxf(acc[0][nt][0], acc[0][nt][2]),
                            fmaxf(acc[1][nt][0], acc[1][nt][2]));
        cmax[nt][1] = fmaxf(fmaxf(acc[0][nt][1], acc[0][nt][3]),
                            fmaxf(acc[1][nt][1], acc[1][nt][3]));
    }
#pragma unroll
    for (int off = 16; off >= 4; off >>= 1)
#pragma unroll
        for (int nt = 0; nt < 8; nt++) {
            cmax[nt][0] = fmaxf(cmax[nt][0], __shfl_xor_sync(0xffffffffu, cmax[nt][0], off));
            cmax[nt][1] = fmaxf(cmax[nt][1], __shfl_xor_sync(0xffffffffu, cmax[nt][1], off));
        }
    if (lane < 4) {
        unsigned* pp = &g_pool[batch * 1024 + col0 + warp_n * 64];
#pragma unroll
        for (int nt = 0; nt < 8; nt++) {
            atomicMax(&pp[nt * 8 + lane * 2], fenc(cmax[nt][0]));
            atomicMax(&pp[nt * 8 + lane * 2 + 1], fenc(cmax[nt][1]));
        }
    }
}

// ---------------- fused MLP head ----------------
__global__ void mlp_kernel(const float* __restrict__ lin1_w,
                           const float* __restrict__ bn6_g, const float* __restrict__ bn6_b,
                           const float* __restrict__ lin2_w, const float* __restrict__ lin2_b,
                           const float* __restrict__ bn7_g, const float* __restrict__ bn7_b,
                           const float* __restrict__ lin3_w, const float* __restrict__ lin3_b,
                           float* __restrict__ out) {
    int b = blockIdx.x, t = threadIdx.x;
    __shared__ float sy[1024];
    __shared__ float s1[512];
    __shared__ float s2[256];
    for (int i = t; i < 1024; i += 256) sy[i] = fdec(g_pool[b * 1024 + i]);
    __syncthreads();
    const float r = rsqrtf(1.0f + 1e-5f);
    for (int j = t; j < 512; j += 256) {
        const float* w = lin1_w + (size_t)j * 1024;
        float acc = 0.f;
        for (int c = 0; c < 1024; c++) acc = fmaf(w[c], sy[c], acc);
        float v = fmaf(acc, bn6_g[j] * r, bn6_b[j]);
        s1[j] = (v >= 0.f) ? v : 0.01f * v;
    }
    __syncthreads();
    {
        const float* w = lin2_w + (size_t)t * 512;
        float acc = lin2_b[t];
        for (int c = 0; c < 512; c++) acc = fmaf(w[c], s1[c], acc);
        float v = fmaf(acc, bn7_g[t] * r, bn7_b[t]);
        s2[t] = (v >= 0.f) ? v : 0.01f * v;
    }
    __syncthreads();
    if (t < 40) {
        const float* w = lin3_w + (size_t)t * 256;
        float acc = lin3_b[t];
        for (int c = 0; c < 256; c++) acc = fmaf(w[c], s2[c], acc);
        out[b * 40 + t] = acc;
    }
}

// ---------------- stream/event lazy init (host-side objects only) ----------------
static cudaStream_t s2 = nullptr;
static cudaEvent_t evFork[5], evJoin[5];
static bool s_init = false;
static void ensure_streams() {
    if (s_init) return;
    cudaStreamCreateWithFlags(&s2, cudaStreamNonBlocking);
    for (int i = 0; i < 5; i++) {
        cudaEventCreateWithFlags(&evFork[i], cudaEventDisableTiming);
        cudaEventCreateWithFlags(&evJoin[i], cudaEventDisableTiming);
    }
    s_init = true;
}

extern "C" void kernel_launch(void* const* d_in, const int* in_sizes, int n_in,
                              void* d_out, int out_size) {
    const float* x       = (const float*)d_in[0];
    const float* conv1_w = (const float*)d_in[1];
    const float* conv1_b = (const float*)d_in[2];
    const float* bn1_g   = (const float*)d_in[3];
    const float* bn1_b   = (const float*)d_in[4];
    const float* conv2_w = (const float*)d_in[5];
    const float* bn2_g   = (const float*)d_in[6];
    const float* bn2_b   = (const float*)d_in[7];
    const float* conv3_w = (const float*)d_in[8];
    const float* bn3_g   = (const float*)d_in[9];
    const float* bn3_b   = (const float*)d_in[10];
    const float* conv4_w = (const float*)d_in[11];
    const float* bn4_g   = (const float*)d_in[12];
    const float* bn4_b   = (const float*)d_in[13];
    const float* conv5_w = (const float*)d_in[14];
    const float* lin1_w  = (const float*)d_in[15];
    const float* bn6_g   = (const float*)d_in[16];
    const float* bn6_b   = (const float*)d_in[17];
    const float* lin2_w  = (const float*)d_in[18];
    const float* lin2_b  = (const float*)d_in[19];
    const float* bn7_g   = (const float*)d_in[20];
    const float* bn7_b   = (const float*)d_in[21];
    const float* lin3_w  = (const float*)d_in[22];
    const float* lin3_b  = (const float*)d_in[23];
    float* out = (float*)d_out;

    ensure_streams();

    // prep on main stream (everything depends on it)
    prep_kernel<<<(WEND + 255) / 256, 256>>>(conv1_w, conv2_w, conv3_w, conv4_w);
    cvtB_kernel<<<1024 * 512 / 256, 256>>>(conv5_w);
    sqnorm1_kernel<<<32, 256>>>(x);

    const long sDist = (long)Npt * Npt;

    // ----- layer 1 (C=3, O=64): fp32 path; feat ∥ (dist, topk) -----
    cudaEventRecord(evFork[0], 0);
    cudaStreamWaitEvent(s2, evFork[0], 0);
    gemm128_kernel<false><<<dim3(64, 1, 1), 256, 0, s2>>>(x, WOFF1, 1, 128, 0);
    cudaEventRecord(evJoin[0], s2);
    gemm128_kernel<true><<<dim3(36, 1, Bsz), 256>>>(x, 0, 0, Npt, sDist);
    topk_kernel<<<Bsz * Npt / 8, 256>>>();
    cudaStreamWaitEvent(0, evJoin[0], 0);
    aggregate_kernel<<<Bsz * Npt, 64>>>(64, conv1_b, bn1_g, bn1_b, 0);

    // ----- layer 2 (C=64, O=64): feat ∥ (dist, topk) -----
    cudaEventRecord(evFork[1], 0);
    cudaStreamWaitEvent(s2, evFork[1], 0);
    mma_gemm_kernel<4, false><<<dim3(64, 1), 256, 0, s2>>>(0, WOFF2, 128);
    cudaEventRecord(evJoin[1], s2);
    mma_gemm_kernel<4, true><<<dim3(8, 8, Bsz), 256>>>(0, 0, 0);
    topk_kernel<<<Bsz * Npt / 8, 256>>>();
    cudaStreamWaitEvent(0, evJoin[1], 0);
    aggregate_kernel<<<Bsz * Npt, 64>>>(64, nullptr, bn2_g, bn2_b, 64);

    // ----- layer 3 (C=64, O=128) -----
    cudaEventRecord(evFork[2], 0);
    cudaStreamWaitEvent(s2, evFork[2], 0);
    mma_gemm_kernel<4, false><<<dim3(64, 2), 256, 0, s2>>>(64, WOFF3, 256);
    cudaEventRecord(evJoin[2], s2);
    mma_gemm_kernel<4, true><<<dim3(8, 8, Bsz), 256>>>(64, 0, 0);
    topk_kernel<<<Bsz * Npt / 8, 256>>>();
    cudaStreamWaitEvent(0, evJoin[2], 0);
    aggregate_kernel<<<Bsz * Npt, 128>>>(128, nullptr, bn3_g, bn3_b, 128);

    // ----- layer 4 (C=128, O=256) -----
    cudaEventRecord(evFork[3], 0);
    cudaStreamWaitEvent(s2, evFork[3], 0);
    mma_gemm_kernel<8, false><<<dim3(64, 4), 256, 0, s2>>>(128, WOFF4, 512);
    cudaEventRecord(evJoin[3], s2);
    mma_gemm_kernel<8, true><<<dim3(8, 8, Bsz), 256>>>(128, 0, 0);
    topk_kernel<<<Bsz * Npt / 8, 256>>>();
    cudaStreamWaitEvent(0, evJoin[3], 0);
    aggregate_kernel<<<Bsz * Npt, 256>>>(256, nullptr, bn4_g, bn4_b, 256);

    // ----- conv5 (K=512) with fused global max-pool -----
    conv5_mma_kernel<<<dim3(64, 8), 256>>>();

    // ----- MLP head -----
    mlp_kernel<<<Bsz, 256>>>(lin1_w, bn6_g, bn6_b, lin2_w, lin2_b,
                             bn7_g, bn7_b, lin3_w, lin3_b, out);
}

// round 13
// speedup vs baseline: 1.0463x; 1.0463x over previous
#include <cuda_runtime.h>
#include <cuda_bf16.h>
#include <cfloat>
#include <cstdint>

#define Bsz 8
#define Npt 1024
#define KNN 20
#define CKS 24   // bf16 row stride in smem (48B: conflict-free, 16B-aligned)
#define BUFB (128 * CKS * 2)   // bytes per smem buffer (6144)

// ---------------- scratch (device globals; no allocation) ----------------
__device__ float    g_xx[Bsz * Npt];                     // squared norms
__device__ float    g_dist[(size_t)Bsz * Npt * Npt];     // dist matrix
__device__ int      g_idx[Bsz * Npt * KNN];              // knn indices
__device__ float    g_Y[(size_t)Bsz * Npt * 512];        // per-layer GEMM output (B*N, 2*O)
__device__ float    g_Weff[92160];                       // folded weights fp32 (layer-1 use)
__device__ unsigned g_pool[Bsz * 1024];                  // global max pool (monotonic-uint)
__device__ __nv_bfloat16 g_Fh[(size_t)8192 * 512];       // features hi (x1|x2|x3|x4)
__device__ __nv_bfloat16 g_Fl[(size_t)8192 * 512];       // features lo
__device__ __nv_bfloat16 g_Wh[92160];                    // folded weights hi
__device__ __nv_bfloat16 g_Wl[92160];                    // folded weights lo
__device__ __nv_bfloat16 g_Bh[(size_t)1024 * 512];       // conv5 weight hi
__device__ __nv_bfloat16 g_Bl[(size_t)1024 * 512];       // conv5 weight lo

// Weff segment offsets (2O x C):  L1 128x3, L2 128x64, L3 256x64, L4 512x128
#define WOFF1 0
#define WOFF2 384
#define WOFF3 8576
#define WOFF4 24960
#define WEND  90496

// monotonic float<->uint encoding
__device__ __forceinline__ unsigned fenc(float v) {
    unsigned u = __float_as_uint(v);
    return (u & 0x80000000u) ? ~u : (u | 0x80000000u);
}
__device__ __forceinline__ float fdec(unsigned u) {
    unsigned f = (u & 0x80000000u) ? (u ^ 0x80000000u) : ~u;
    return __uint_as_float(f);
}

// bf16 mma.sync m16n8k16 (legacy tensor path — compiles for compute_103)
__device__ __forceinline__ void mma16816(float (&d)[4], const uint32_t (&a)[4],
                                         const uint32_t (&b)[2]) {
    asm volatile("mma.sync.aligned.m16n8k16.row.col.f32.bf16.bf16.f32 "
                 "{%0,%1,%2,%3}, {%4,%5,%6,%7}, {%8,%9}, {%0,%1,%2,%3};"
                 : "+f"(d[0]), "+f"(d[1]), "+f"(d[2]), "+f"(d[3])
                 : "r"(a[0]), "r"(a[1]), "r"(a[2]), "r"(a[3]), "r"(b[0]), "r"(b[1]));
}

// cp.async helpers (sm_80+ PTX)
__device__ __forceinline__ void cpa16(uint32_t saddr, const void* g) {
    asm volatile("cp.async.cg.shared.global [%0], [%1], 16;" :: "r"(saddr), "l"(g));
}
#define CPA_COMMIT() asm volatile("cp.async.commit_group;")
#define CPA_WAIT0()  asm volatile("cp.async.wait_group 0;")

// ---------------- prep: fold weights (fp32 + hi/lo bf16) + init pool ----------------
__device__ __forceinline__ float weff_val(const float* __restrict__ W, int O, int C, int i) {
    int j = i / C, c = i - j * C;
    if (j < O) return W[(size_t)j * 2 * C + c];
    int jo = j - O;
    return W[(size_t)jo * 2 * C + C + c] - W[(size_t)jo * 2 * C + c];
}
__global__ void prep_kernel(const float* __restrict__ w1, const float* __restrict__ w2,
                            const float* __restrict__ w3, const float* __restrict__ w4) {
    int i = blockIdx.x * 256 + threadIdx.x;
    if (i < Bsz * 1024) g_pool[i] = 0u;
    if (i >= WEND) return;
    float v;
    if (i < WOFF2)      v = weff_val(w1, 64, 3, i - WOFF1);
    else if (i < WOFF3) v = weff_val(w2, 64, 64, i - WOFF2);
    else if (i < WOFF4) v = weff_val(w3, 128, 64, i - WOFF3);
    else                v = weff_val(w4, 256, 128, i - WOFF4);
    g_Weff[i] = v;
    __nv_bfloat16 h = __float2bfloat16(v);
    g_Wh[i] = h;
    g_Wl[i] = __float2bfloat16(v - __bfloat162float(h));
}

__global__ void sqnorm1_kernel(const float* __restrict__ x) {
    int i = blockIdx.x * 256 + threadIdx.x;
    if (i >= Bsz * Npt) return;
    const float* p = x + (size_t)i * 3;
    g_xx[i] = p[0] * p[0] + p[1] * p[1] + p[2] * p[2];
}

// ---------------- layer-1 fp32 GEMM (K=3): DIST(SYRK) and FEAT ----------------
template <bool DIST>
__global__ void __launch_bounds__(256, 2)
gemm128_kernel(const float* __restrict__ Aext, int Boff, int Csel, int ldc, long sC,
               int zbase) {
    constexpr int KDIM = 3;
    __shared__ float As[16][132];
    __shared__ float Bs[16][132];

    const int tid = threadIdx.x;
    const int tx = tid & 15, ty = tid >> 4;
    const int z = blockIdx.z + zbase;
    const int lda = 3;

    int bx, by;
    if (DIST) {
        int t = blockIdx.x;
        bx = 0;
        while (t >= bx + 1) { t -= bx + 1; bx++; }
        by = t;
    } else {
        bx = blockIdx.x; by = blockIdx.y;
    }
    const int row0 = bx * 128;
    const int col0 = by * 128;

    const float* A = Aext + (size_t)z * (DIST ? 3 * Npt : 0);
    const float* Bt;
    int ldbb;
    if (DIST) { Bt = A; ldbb = lda; }
    else      { Bt = g_Weff + Boff; ldbb = KDIM; }

    float acc[8][8];
#pragma unroll
    for (int i = 0; i < 8; i++)
#pragma unroll
        for (int j = 0; j < 8; j++) acc[i][j] = 0.f;

#pragma unroll
    for (int l = 0; l < 8; l++) {
        int i = tid + l * 256;
        int r = i >> 4, k = i & 15;
        As[k][r] = (k < KDIM) ? A[(size_t)(row0 + r) * lda + k] : 0.f;
        Bs[k][r] = (k < KDIM) ? Bt[(size_t)(col0 + r) * ldbb + k] : 0.f;
    }
    __syncthreads();
#pragma unroll
    for (int k = 0; k < 3; k++) {
        float4 a0 = *(const float4*)&As[k][ty * 4];
        float4 a1 = *(const float4*)&As[k][ty * 4 + 64];
        float4 b0 = *(const float4*)&Bs[k][tx * 4];
        float4 b1 = *(const float4*)&Bs[k][tx * 4 + 64];
        float av[8] = {a0.x, a0.y, a0.z, a0.w, a1.x, a1.y, a1.z, a1.w};
        float bv[8] = {b0.x, b0.y, b0.z, b0.w, b1.x, b1.y, b1.z, b1.w};
#pragma unroll
        for (int i = 0; i < 8; i++)
#pragma unroll
            for (int j = 0; j < 8; j++)
                acc[i][j] = fmaf(av[i], bv[j], acc[i][j]);
    }

    float* Cp = ((Csel == 0) ? g_dist : g_Y) + (size_t)z * sC;

    if (DIST) {
        const float* xx = g_xx + (size_t)z * Npt;
        float xr[8], xc8[8];
#pragma unroll
        for (int i = 0; i < 8; i++) {
            xr[i]  = xx[row0 + (i >> 2) * 64 + ty * 4 + (i & 3)];
            xc8[i] = xx[col0 + (i >> 2) * 64 + tx * 4 + (i & 3)];
        }
#pragma unroll
        for (int i = 0; i < 8; i++) {
            int r = row0 + (i >> 2) * 64 + ty * 4 + (i & 3);
#pragma unroll
            for (int cs = 0; cs < 2; cs++) {
                float4 o;
                o.x = 2.f * acc[i][cs * 4 + 0] - xr[i] - xc8[cs * 4 + 0];
                o.y = 2.f * acc[i][cs * 4 + 1] - xr[i] - xc8[cs * 4 + 1];
                o.z = 2.f * acc[i][cs * 4 + 2] - xr[i] - xc8[cs * 4 + 2];
                o.w = 2.f * acc[i][cs * 4 + 3] - xr[i] - xc8[cs * 4 + 3];
                *(float4*)&Cp[(size_t)r * ldc + col0 + cs * 64 + tx * 4] = o;
            }
        }
        if (bx != by) {
#pragma unroll
            for (int j = 0; j < 8; j++) {
                int c = col0 + (j >> 2) * 64 + tx * 4 + (j & 3);
#pragma unroll
                for (int rs = 0; rs < 2; rs++) {
                    float4 o;
                    o.x = 2.f * acc[rs * 4 + 0][j] - xr[rs * 4 + 0] - xc8[j];
                    o.y = 2.f * acc[rs * 4 + 1][j] - xr[rs * 4 + 1] - xc8[j];
                    o.z = 2.f * acc[rs * 4 + 2][j] - xr[rs * 4 + 2] - xc8[j];
                    o.w = 2.f * acc[rs * 4 + 3][j] - xr[rs * 4 + 3] - xc8[j];
                    *(float4*)&Cp[(size_t)c * ldc + row0 + rs * 64 + ty * 4] = o;
                }
            }
        }
    } else {
#pragma unroll
        for (int i = 0; i < 8; i++) {
            int r = row0 + (i >> 2) * 64 + ty * 4 + (i & 3);
#pragma unroll
            for (int cs = 0; cs < 2; cs++) {
                float4 o;
                o.x = acc[i][cs * 4 + 0];
                o.y = acc[i][cs * 4 + 1];
                o.z = acc[i][cs * 4 + 2];
                o.w = acc[i][cs * 4 + 3];
                *(float4*)&Cp[(size_t)r * ldc + col0 + cs * 64 + tx * 4] = o;
            }
        }
    }
}

// ---------------- unified bf16-split mma GEMM (layers 2-4) ----------------
// cp.async double-buffered, occupancy 2, one __syncthreads per K-chunk.
template <int KCHUNKS, bool DIST>
__global__ void __launch_bounds__(256, 2)
mma_gemm_kernel(int chanoff, int woff, int twoO, int zbase) {
    __shared__ __nv_bfloat16 sAh[2][128 * CKS];
    __shared__ __nv_bfloat16 sAl[2][128 * CKS];
    __shared__ __nv_bfloat16 sBh[2][128 * CKS];
    __shared__ __nv_bfloat16 sBl[2][128 * CKS];

    const int tid = threadIdx.x;
    const int wid = tid >> 5, lane = tid & 31;
    const int warp_m = wid & 3, warp_n = wid >> 2;
    const int lr = tid >> 1, lkb = (tid & 1) * 8;
    const int grp = lane >> 2, kq = (lane & 3) * 2;
    const int soffB = (lr * CKS + lkb) * 2;   // bytes

    const int zz = blockIdx.z + zbase;
    size_t aoff, boff;
    const __nv_bfloat16 *Bh_, *Bl_;
    if (DIST) {
        aoff = (size_t)(zz * 1024 + blockIdx.x * 128 + lr) * 512 + chanoff + lkb;
        boff = (size_t)(zz * 1024 + blockIdx.y * 128 + lr) * 512 + chanoff + lkb;
        Bh_ = g_Fh; Bl_ = g_Fl;
    } else {
        aoff = (size_t)(blockIdx.x * 128 + lr) * 512 + chanoff + lkb;
        boff = (size_t)(blockIdx.y * 128 + lr) * (KCHUNKS * 16) + lkb;
        Bh_ = g_Wh + woff; Bl_ = g_Wl + woff;
    }

    const uint32_t sah = (uint32_t)__cvta_generic_to_shared(sAh[0]) + soffB;
    const uint32_t sal = (uint32_t)__cvta_generic_to_shared(sAl[0]) + soffB;
    const uint32_t sbh = (uint32_t)__cvta_generic_to_shared(sBh[0]) + soffB;
    const uint32_t sbl = (uint32_t)__cvta_generic_to_shared(sBl[0]) + soffB;

    float acc[2][8][4];
#pragma unroll
    for (int mt = 0; mt < 2; mt++)
#pragma unroll
        for (int nt = 0; nt < 8; nt++)
#pragma unroll
            for (int f = 0; f < 4; f++) acc[mt][nt][f] = 0.f;

    // issue chunk 0 into buf 0
    cpa16(sah, &g_Fh[aoff]);
    cpa16(sal, &g_Fl[aoff]);
    cpa16(sbh, &Bh_[boff]);
    cpa16(sbl, &Bl_[boff]);
    CPA_COMMIT();
    CPA_WAIT0();
    __syncthreads();

#pragma unroll
    for (int ch = 0; ch < KCHUNKS; ch++) {
        const int buf = ch & 1;
        if (ch + 1 < KCHUNKS) {
            const int nb = (ch + 1) & 1;
            const int kk = (ch + 1) * 16;
            cpa16(sah + nb * BUFB, &g_Fh[aoff + kk]);
            cpa16(sal + nb * BUFB, &g_Fl[aoff + kk]);
            cpa16(sbh + nb * BUFB, &Bh_[boff + kk]);
            cpa16(sbl + nb * BUFB, &Bl_[boff + kk]);
            CPA_COMMIT();
        }
        uint32_t ah[2][4], al[2][4], bh[8][2], bl[8][2];
#pragma unroll
        for (int mt = 0; mt < 2; mt++) {
            int r0 = (warp_m * 32 + mt * 16 + grp) * CKS;
            ah[mt][0] = *(const uint32_t*)&sAh[buf][r0 + kq];
            ah[mt][1] = *(const uint32_t*)&sAh[buf][r0 + 8 * CKS + kq];
            ah[mt][2] = *(const uint32_t*)&sAh[buf][r0 + kq + 8];
            ah[mt][3] = *(const uint32_t*)&sAh[buf][r0 + 8 * CKS + kq + 8];
            al[mt][0] = *(const uint32_t*)&sAl[buf][r0 + kq];
            al[mt][1] = *(const uint32_t*)&sAl[buf][r0 + 8 * CKS + kq];
            al[mt][2] = *(const uint32_t*)&sAl[buf][r0 + kq + 8];
            al[mt][3] = *(const uint32_t*)&sAl[buf][r0 + 8 * CKS + kq + 8];
        }
#pragma unroll
        for (int nt = 0; nt < 8; nt++) {
            int n0 = (warp_n * 64 + nt * 8 + grp) * CKS;
            bh[nt][0] = *(const uint32_t*)&sBh[buf][n0 + kq];
            bh[nt][1] = *(const uint32_t*)&sBh[buf][n0 + kq + 8];
            bl[nt][0] = *(const uint32_t*)&sBl[buf][n0 + kq];
            bl[nt][1] = *(const uint32_t*)&sBl[buf][n0 + kq + 8];
        }
#pragma unroll
        for (int mt = 0; mt < 2; mt++)
#pragma unroll
            for (int nt = 0; nt < 8; nt++) {
                mma16816(acc[mt][nt], ah[mt], bh[nt]);
                mma16816(acc[mt][nt], ah[mt], bl[nt]);
                mma16816(acc[mt][nt], al[mt], bh[nt]);
            }
        if (ch + 1 < KCHUNKS) {
            CPA_WAIT0();
            __syncthreads();
        }
    }

    if (DIST) {
        const float* xx = g_xx + (size_t)zz * Npt;
        float* Cp = g_dist + (size_t)zz * Npt * Npt;
        const int rb = blockIdx.x * 128 + warp_m * 32;
        const int cb = blockIdx.y * 128 + warp_n * 64;
        float xr[2][2];
#pragma unroll
        for (int mt = 0; mt < 2; mt++) {
            xr[mt][0] = xx[rb + mt * 16 + grp];
            xr[mt][1] = xx[rb + mt * 16 + grp + 8];
        }
#pragma unroll
        for (int nt = 0; nt < 8; nt++) {
            int c = cb + nt * 8 + kq;
            float xc0 = xx[c], xc1 = xx[c + 1];
#pragma unroll
            for (int mt = 0; mt < 2; mt++) {
                int r = rb + mt * 16 + grp;
                *(float2*)&Cp[(size_t)r * Npt + c] = make_float2(
                    2.f * acc[mt][nt][0] - xr[mt][0] - xc0,
                    2.f * acc[mt][nt][1] - xr[mt][0] - xc1);
                *(float2*)&Cp[(size_t)(r + 8) * Npt + c] = make_float2(
                    2.f * acc[mt][nt][2] - xr[mt][1] - xc0,
                    2.f * acc[mt][nt][3] - xr[mt][1] - xc1);
            }
        }
    } else {
        const int rb = blockIdx.x * 128 + warp_m * 32;
        const int cb = blockIdx.y * 128 + warp_n * 64;
#pragma unroll
        for (int mt = 0; mt < 2; mt++) {
            int r = rb + mt * 16 + grp;
#pragma unroll
            for (int nt = 0; nt < 8; nt++) {
                int c = cb + nt * 8 + kq;
                *(float2*)&g_Y[(size_t)r * twoO + c] =
                    make_float2(acc[mt][nt][0], acc[mt][nt][1]);
                *(float2*)&g_Y[(size_t)(r + 8) * twoO + c] =
                    make_float2(acc[mt][nt][2], acc[mt][nt][3]);
            }
        }
    }
}

// ---------------- top-K (K=20): warp/row, REDUX select + 2-level rescan ----------------
__global__ void topk_kernel(int rowbase) {
    int row = rowbase + (blockIdx.x << 3) + (threadIdx.x >> 5);
    int lane = threadIdx.x & 31;
    const float* rp = g_dist + (size_t)row * Npt + lane;
    float v[32];
#pragma unroll
    for (int j = 0; j < 32; j++) v[j] = rp[j * 32];
    float gm[4];
    int gj[4];
#pragma unroll
    for (int g = 0; g < 4; g++) {
        gm[g] = v[g * 8]; gj[g] = g * 8;
#pragma unroll
        for (int j = 1; j < 8; j++)
            if (v[g * 8 + j] > gm[g]) { gm[g] = v[g * 8 + j]; gj[g] = g * 8 + j; }
    }
    float lm = gm[0];
    int li = gj[0];
#pragma unroll
    for (int g = 1; g < 4; g++)
        if (gm[g] > lm) { lm = gm[g]; li = gj[g]; }
    int gi = li * 32 + lane;

    for (int k = 0; k < KNN; k++) {
        unsigned mykey = fenc(lm);
        unsigned wmax = __reduce_max_sync(0xffffffffu, mykey);
        unsigned cand = (mykey == wmax) ? (unsigned)gi : 0xFFFFFFFFu;
        unsigned wini = __reduce_min_sync(0xffffffffu, cand);
        if (lane == 0) g_idx[row * KNN + k] = (int)wini;
        if (mykey == wmax && gi == (int)wini) {
            int jr = li, gr = li >> 3;
#pragma unroll
            for (int g = 0; g < 4; g++)
                if (g == gr) {
#pragma unroll
                    for (int j = 0; j < 8; j++)
                        if (g * 8 + j == jr) v[g * 8 + j] = -FLT_MAX;
                    gm[g] = v[g * 8]; gj[g] = g * 8;
#pragma unroll
                    for (int j = 1; j < 8; j++)
                        if (v[g * 8 + j] > gm[g]) { gm[g] = v[g * 8 + j]; gj[g] = g * 8 + j; }
                }
            lm = gm[0]; li = gj[0];
#pragma unroll
            for (int g = 1; g < 4; g++)
                if (gm[g] > lm) { lm = gm[g]; li = gj[g]; }
            gi = li * 32 + lane;
        }
    }
}

// ---- gather + bias + bn + lrelu + max over K; emit bf16 hi/lo features + sqnorm ----
__global__ void aggregate_kernel(int O, const float* __restrict__ bias,
                                 const float* __restrict__ bng, const float* __restrict__ bnb,
                                 int outoff) {
    int bn = blockIdx.x;
    int b = bn >> 10;
    int o = threadIdx.x;
    __shared__ int sidx[KNN];
    __shared__ float sp[8];
    if (o < KNN) sidx[o] = g_idx[bn * KNN + o];
    __syncthreads();
    int twoO = 2 * O;
    const float* Yrow = g_Y + (size_t)bn * twoO;
    float ctr = Yrow[O + o];
    if (bias) ctr += bias[o];
    float scale = bng[o] * rsqrtf(1.0f + 1e-5f);
    float shift = bnb[o];
    const float* Yb = g_Y + (size_t)(b << 10) * twoO;
    float m = -FLT_MAX;
#pragma unroll
    for (int k = 0; k < KNN; k++) {
        float v = Yb[(size_t)sidx[k] * twoO + o] + ctr;
        v = fmaf(v, scale, shift);
        v = (v >= 0.f) ? v : 0.01f * v;
        m = fmaxf(m, v);
    }
    __nv_bfloat16 h = __float2bfloat16(m);
    g_Fh[(size_t)bn * 512 + outoff + o] = h;
    g_Fl[(size_t)bn * 512 + outoff + o] = __float2bfloat16(m - __bfloat162float(h));
    float s = m * m;
#pragma unroll
    for (int off = 16; off; off >>= 1) s += __shfl_xor_sync(0xffffffffu, s, off);
    if ((o & 31) == 0) sp[o >> 5] = s;
    __syncthreads();
    if (o == 0) {
        float t = 0.f;
        int nw = O >> 5;
        for (int w = 0; w < nw; w++) t += sp[w];
        g_xx[bn] = t;
    }
}

// ---------------- conv5 weight split ----------------
__global__ void cvtB_kernel(const float* __restrict__ w5) {
    int i = blockIdx.x * 256 + threadIdx.x;          // [0, 1024*512)
    float x = w5[i];
    __nv_bfloat16 h = __float2bfloat16(x);
    g_Bh[i] = h;
    g_Bl[i] = __float2bfloat16(x - __bfloat162float(h));
}

// ------- conv5: bf16-split mma GEMM (K=512), cp.async pipeline, fused max-pool -------
__global__ void __launch_bounds__(256, 2) conv5_mma_kernel() {
    __shared__ __nv_bfloat16 sAh[2][128 * CKS];
    __shared__ __nv_bfloat16 sAl[2][128 * CKS];
    __shared__ __nv_bfloat16 sBh[2][128 * CKS];
    __shared__ __nv_bfloat16 sBl[2][128 * CKS];

    const int tid = threadIdx.x;
    const int wid = tid >> 5, lane = tid & 31;
    const int warp_m = wid & 3, warp_n = wid >> 2;
    const int row0 = blockIdx.x * 128;
    const int col0 = blockIdx.y * 128;
    const int batch = row0 >> 10;

    const int lr = tid >> 1;
    const int lkb = (tid & 1) * 8;
    const size_t aoff = (size_t)(row0 + lr) * 512 + lkb;
    const size_t boff = (size_t)(col0 + lr) * 512 + lkb;
    const int soffB = (lr * CKS + lkb) * 2;

    const uint32_t sah = (uint32_t)__cvta_generic_to_shared(sAh[0]) + soffB;
    const uint32_t sal = (uint32_t)__cvta_generic_to_shared(sAl[0]) + soffB;
    const uint32_t sbh = (uint32_t)__cvta_generic_to_shared(sBh[0]) + soffB;
    const uint32_t sbl = (uint32_t)__cvta_generic_to_shared(sBl[0]) + soffB;

    float acc[2][8][4];
#pragma unroll
    for (int mt = 0; mt < 2; mt++)
#pragma unroll
        for (int nt = 0; nt < 8; nt++)
#pragma unroll
            for (int f = 0; f < 4; f++) acc[mt][nt][f] = 0.f;

    cpa16(sah, &g_Fh[aoff]);
    cpa16(sal, &g_Fl[aoff]);
    cpa16(sbh, &g_Bh[boff]);
    cpa16(sbl, &g_Bl[boff]);
    CPA_COMMIT();
    CPA_WAIT0();
    __syncthreads();

    const int grp = lane >> 2;
    const int kq = (lane & 3) * 2;

    for (int ch = 0; ch < 32; ch++) {
        const int buf = ch & 1;
        if (ch < 31) {
            const int nb = (ch + 1) & 1;
            const int kk = (ch + 1) * 16;
            cpa16(sah + nb * BUFB, &g_Fh[aoff + kk]);
            cpa16(sal + nb * BUFB, &g_Fl[aoff + kk]);
            cpa16(sbh + nb * BUFB, &g_Bh[boff + kk]);
            cpa16(sbl + nb * BUFB, &g_Bl[boff + kk]);
            CPA_COMMIT();
        }
        uint32_t ah[2][4], al[2][4], bh[8][2], bl[8][2];
#pragma unroll
        for (int mt = 0; mt < 2; mt++) {
            int r0 = (warp_m * 32 + mt * 16 + grp) * CKS;
            ah[mt][0] = *(const uint32_t*)&sAh[buf][r0 + kq];
            ah[mt][1] = *(const uint32_t*)&sAh[buf][r0 + 8 * CKS + kq];
            ah[mt][2] = *(const uint32_t*)&sAh[buf][r0 + kq + 8];
            ah[mt][3] = *(const uint32_t*)&sAh[buf][r0 + 8 * CKS + kq + 8];
            al[mt][0] = *(const uint32_t*)&sAl[buf][r0 + kq];
            al[mt][1] = *(const uint32_t*)&sAl[buf][r0 + 8 * CKS + kq];
            al[mt][2] = *(const uint32_t*)&sAl[buf][r0 + kq + 8];
            al[mt][3] = *(const uint32_t*)&sAl[buf][r0 + 8 * CKS + kq + 8];
        }
#pragma unroll
        for (int nt = 0; nt < 8; nt++) {
            int n0 = (warp_n * 64 + nt * 8 + grp) * CKS;
            bh[nt][0] = *(const uint32_t*)&sBh[buf][n0 + kq];
            bh[nt][1] = *(const uint32_t*)&sBh[buf][n0 + kq + 8];
            bl[nt][0] = *(const uint32_t*)&sBl[buf][n0 + kq];
            bl[nt][1] = *(const uint32_t*)&sBl[buf][n0 + kq + 8];
        }
#pragma unroll
        for (int mt = 0; mt < 2; mt++)
#pragma unroll
            for (int nt = 0; nt < 8; nt++) {
                mma16816(acc[mt][nt], ah[mt], bh[nt]);
                mma16816(acc[mt][nt], ah[mt], bl[nt]);
                mma16816(acc[mt][nt], al[mt], bh[nt]);
            }
        if (ch < 31) {
            CPA_WAIT0();
            __syncthreads();
        }
    }

    float cmax[8][2];
#pragma unroll
    for (int nt = 0; nt < 8; nt++) {
        cmax[nt][0] = fmaxf(fmaxf(acc[0][nt][0], acc[0][nt][2]),
                            fmaxf(acc[1][nt][0], acc[1][nt][2]));
        cmax[nt][1] = fmaxf(fmaxf(acc[0][nt][1], acc[0][nt][3]),
                            fmaxf(acc[1][nt][1], acc[1][nt][3]));
    }
#pragma unroll
    for (int off = 16; off >= 4; off >>= 1)
#pragma unroll
        for (int nt = 0; nt < 8; nt++) {
            cmax[nt][0] = fmaxf(cmax[nt][0], __shfl_xor_sync(0xffffffffu, cmax[nt][0], off));
            cmax[nt][1] = fmaxf(cmax[nt][1], __shfl_xor_sync(0xffffffffu, cmax[nt][1], off));
        }
    if (lane < 4) {
        unsigned* pp = &g_pool[batch * 1024 + col0 + warp_n * 64];
#pragma unroll
        for (int nt = 0; nt < 8; nt++) {
            atomicMax(&pp[nt * 8 + lane * 2], fenc(cmax[nt][0]));
            atomicMax(&pp[nt * 8 + lane * 2 + 1], fenc(cmax[nt][1]));
        }
    }
}

// ---------------- fused MLP head ----------------
__global__ void mlp_kernel(const float* __restrict__ lin1_w,
                           const float* __restrict__ bn6_g, const float* __restrict__ bn6_b,
                           const float* __restrict__ lin2_w, const float* __restrict__ lin2_b,
                           const float* __restrict__ bn7_g, const float* __restrict__ bn7_b,
                           const float* __restrict__ lin3_w, const float* __restrict__ lin3_b,
                           float* __restrict__ out) {
    int b = blockIdx.x, t = threadIdx.x;
    __shared__ float sy[1024];
    __shared__ float s1[512];
    __shared__ float s2s[256];
    for (int i = t; i < 1024; i += 256) sy[i] = fdec(g_pool[b * 1024 + i]);
    __syncthreads();
    const float r = rsqrtf(1.0f + 1e-5f);
    for (int j = t; j < 512; j += 256) {
        const float* w = lin1_w + (size_t)j * 1024;
        float acc = 0.f;
        for (int c = 0; c < 1024; c++) acc = fmaf(w[c], sy[c], acc);
        float v = fmaf(acc, bn6_g[j] * r, bn6_b[j]);
        s1[j] = (v >= 0.f) ? v : 0.01f * v;
    }
    __syncthreads();
    {
        const float* w = lin2_w + (size_t)t * 512;
        float acc = lin2_b[t];
        for (int c = 0; c < 512; c++) acc = fmaf(w[c], s1[c], acc);
        float v = fmaf(acc, bn7_g[t] * r, bn7_b[t]);
        s2s[t] = (v >= 0.f) ? v : 0.01f * v;
    }
    __syncthreads();
    if (t < 40) {
        const float* w = lin3_w + (size_t)t * 256;
        float acc = lin3_b[t];
        for (int c = 0; c < 256; c++) acc = fmaf(w[c], s2s[c], acc);
        out[b * 40 + t] = acc;
    }
}

// ---------------- stream/event lazy init (host-side objects only) ----------------
static cudaStream_t s2 = nullptr, s3 = nullptr;
static cudaEvent_t evFork[4], evJoin[4], evD[4], evT[4];
static bool s_init = false;
static void ensure_streams() {
    if (s_init) return;
    cudaStreamCreateWithFlags(&s2, cudaStreamNonBlocking);
    cudaStreamCreateWithFlags(&s3, cudaStreamNonBlocking);
    for (int i = 0; i < 4; i++) {
        cudaEventCreateWithFlags(&evFork[i], cudaEventDisableTiming);
        cudaEventCreateWithFlags(&evJoin[i], cudaEventDisableTiming);
        cudaEventCreateWithFlags(&evD[i], cudaEventDisableTiming);
        cudaEventCreateWithFlags(&evT[i], cudaEventDisableTiming);
    }
    s_init = true;
}

extern "C" void kernel_launch(void* const* d_in, const int* in_sizes, int n_in,
                              void* d_out, int out_size) {
    const float* x       = (const float*)d_in[0];
    const float* conv1_w = (const float*)d_in[1];
    const float* conv1_b = (const float*)d_in[2];
    const float* bn1_g   = (const float*)d_in[3];
    const float* bn1_b   = (const float*)d_in[4];
    const float* conv2_w = (const float*)d_in[5];
    const float* bn2_g   = (const float*)d_in[6];
    const float* bn2_b   = (const float*)d_in[7];
    const float* conv3_w = (const float*)d_in[8];
    const float* bn3_g   = (const float*)d_in[9];
    const float* bn3_b   = (const float*)d_in[10];
    const float* conv4_w = (const float*)d_in[11];
    const float* bn4_g   = (const float*)d_in[12];
    const float* bn4_b   = (const float*)d_in[13];
    const float* conv5_w = (const float*)d_in[14];
    const float* lin1_w  = (const float*)d_in[15];
    const float* bn6_g   = (const float*)d_in[16];
    const float* bn6_b   = (const float*)d_in[17];
    const float* lin2_w  = (const float*)d_in[18];
    const float* lin2_b  = (const float*)d_in[19];
    const float* bn7_g   = (const float*)d_in[20];
    const float* bn7_b   = (const float*)d_in[21];
    const float* lin3_w  = (const float*)d_in[22];
    const float* lin3_b  = (const float*)d_in[23];
    float* out = (float*)d_out;

    ensure_streams();

    // prep on main stream (everything depends on it)
    prep_kernel<<<(WEND + 255) / 256, 256>>>(conv1_w, conv2_w, conv3_w, conv4_w);
    cvtB_kernel<<<1024 * 512 / 256, 256>>>(conv5_w);
    sqnorm1_kernel<<<32, 256>>>(x);

    const long sDist = (long)Npt * Npt;

    // ----- layer 1 (C=3, O=64): feat ∥ (dist½₁ → (topk½₁ ∥ dist½₂) → topk½₂) -----
    cudaEventRecord(evFork[0], 0);
    cudaStreamWaitEvent(s2, evFork[0], 0);
    gemm128_kernel<false><<<dim3(64, 1, 1), 256, 0, s2>>>(x, WOFF1, 1, 128, 0, 0);
    cudaEventRecord(evJoin[0], s2);
    gemm128_kernel<true><<<dim3(36, 1, 4), 256>>>(x, 0, 0, Npt, sDist, 0);
    cudaEventRecord(evD[0], 0);
    gemm128_kernel<true><<<dim3(36, 1, 4), 256>>>(x, 0, 0, Npt, sDist, 4);
    cudaStreamWaitEvent(s3, evD[0], 0);
    topk_kernel<<<512, 256, 0, s3>>>(0);
    cudaEventRecord(evT[0], s3);
    topk_kernel<<<512, 256>>>(4096);
    cudaStreamWaitEvent(0, evJoin[0], 0);
    cudaStreamWaitEvent(0, evT[0], 0);
    aggregate_kernel<<<Bsz * Npt, 64>>>(64, conv1_b, bn1_g, bn1_b, 0);

    // ----- layer 2 (C=64, O=64) -----
    cudaEventRecord(evFork[1], 0);
    cudaStreamWaitEvent(s2, evFork[1], 0);
    mma_gemm_kernel<4, false><<<dim3(64, 1), 256, 0, s2>>>(0, WOFF2, 128, 0);
    cudaEventRecord(evJoin[1], s2);
    mma_gemm_kernel<4, true><<<dim3(8, 8, 4), 256>>>(0, 0, 0, 0);
    cudaEventRecord(evD[1], 0);
    mma_gemm_kernel<4, true><<<dim3(8, 8, 4), 256>>>(0, 0, 0, 4);
    cudaStreamWaitEvent(s3, evD[1], 0);
    topk_kernel<<<512, 256, 0, s3>>>(0);
    cudaEventRecord(evT[1], s3);
    topk_kernel<<<512, 256>>>(4096);
    cudaStreamWaitEvent(0, evJoin[1], 0);
    cudaStreamWaitEvent(0, evT[1], 0);
    aggregate_kernel<<<Bsz * Npt, 64>>>(64, nullptr, bn2_g, bn2_b, 64);

    // ----- layer 3 (C=64, O=128) -----
    cudaEventRecord(evFork[2], 0);
    cudaStreamWaitEvent(s2, evFork[2], 0);
    mma_gemm_kernel<4, false><<<dim3(64, 2), 256, 0, s2>>>(64, WOFF3, 256, 0);
    cudaEventRecord(evJoin[2], s2);
    mma_gemm_kernel<4, true><<<dim3(8, 8, 4), 256>>>(64, 0, 0, 0);
    cudaEventRecord(evD[2], 0);
    mma_gemm_kernel<4, true><<<dim3(8, 8, 4), 256>>>(64, 0, 0, 4);
    cudaStreamWaitEvent(s3, evD[2], 0);
    topk_kernel<<<512, 256, 0, s3>>>(0);
    cudaEventRecord(evT[2], s3);
    topk_kernel<<<512, 256>>>(4096);
    cudaStreamWaitEvent(0, evJoin[2], 0);
    cudaStreamWaitEvent(0, evT[2], 0);
    aggregate_kernel<<<Bsz * Npt, 128>>>(128, nullptr, bn3_g, bn3_b, 128);

    // ----- layer 4 (C=128, O=256) -----
    cudaEventRecord(evFork[3], 0);
    cudaStreamWaitEvent(s2, evFork[3], 0);
    mma_gemm_kernel<8, false><<<dim3(64, 4), 256, 0, s2>>>(128, WOFF4, 512, 0);
    cudaEventRecord(evJoin[3], s2);
    mma_gemm_kernel<8, true><<<dim3(8, 8, 4), 256>>>(128, 0, 0, 0);
    cudaEventRecord(evD[3], 0);
    mma_gemm_kernel<8, true><<<dim3(8, 8, 4), 256>>>(128, 0, 0, 4);
    cudaStreamWaitEvent(s3, evD[3], 0);
    topk_kernel<<<512, 256, 0, s3>>>(0);
    cudaEventRecord(evT[3], s3);
    topk_kernel<<<512, 256>>>(4096);
    cudaStreamWaitEvent(0, evJoin[3], 0);
    cudaStreamWaitEvent(0, evT[3], 0);
    aggregate_kernel<<<Bsz * Npt, 256>>>(256, nullptr, bn4_g, bn4_b, 256);

    // ----- conv5 (K=512) with fused global max-pool -----
    conv5_mma_kernel<<<dim3(64, 8), 256>>>();

    // ----- MLP head -----
    mlp_kernel<<<Bsz, 256>>>(lin1_w, bn6_g, bn6_b, lin2_w, lin2_b,
                             bn7_g, bn7_b, lin3_w, lin3_b, out);
}

// round 14
// speedup vs baseline: 1.0993x; 1.0507x over previous
#include <cuda_runtime.h>
#include <cuda_bf16.h>
#include <cfloat>
#include <cstdint>

#define Bsz 8
#define Npt 1024
#define KNN 20
#define CKS 24   // bf16 row stride in smem (48B: conflict-free, 16B-aligned)
#define BUFB (128 * CKS * 2)   // bytes per smem buffer (6144)

// ---------------- scratch (device globals; no allocation) ----------------
__device__ float    g_xx[Bsz * Npt];                     // squared norms
__device__ float    g_dist[(size_t)Bsz * Npt * Npt];     // dist matrix
__device__ int      g_idx[Bsz * Npt * KNN];              // knn indices
__device__ float    g_Y[(size_t)Bsz * Npt * 512];        // per-layer GEMM output (B*N, 2*O)
__device__ float    g_C5[(size_t)Bsz * Npt * 1024];      // conv5 partial C (split-K)
__device__ float    g_Weff[92160];                       // folded weights fp32 (layer-1 use)
__device__ unsigned g_pool[Bsz * 1024];                  // global max pool (monotonic-uint)
__device__ __nv_bfloat16 g_Fh[(size_t)8192 * 512];       // features hi (x1|x2|x3|x4)
__device__ __nv_bfloat16 g_Fl[(size_t)8192 * 512];       // features lo
__device__ __nv_bfloat16 g_Wh[92160];                    // folded weights hi
__device__ __nv_bfloat16 g_Wl[92160];                    // folded weights lo
__device__ __nv_bfloat16 g_Bh[(size_t)1024 * 512];       // conv5 weight hi
__device__ __nv_bfloat16 g_Bl[(size_t)1024 * 512];       // conv5 weight lo

// Weff segment offsets (2O x C):  L1 128x3, L2 128x64, L3 256x64, L4 512x128
#define WOFF1 0
#define WOFF2 384
#define WOFF3 8576
#define WOFF4 24960
#define WEND  90496

// monotonic float<->uint encoding
__device__ __forceinline__ unsigned fenc(float v) {
    unsigned u = __float_as_uint(v);
    return (u & 0x80000000u) ? ~u : (u | 0x80000000u);
}
__device__ __forceinline__ float fdec(unsigned u) {
    unsigned f = (u & 0x80000000u) ? (u ^ 0x80000000u) : ~u;
    return __uint_as_float(f);
}

// bf16 mma.sync m16n8k16 (legacy tensor path — compiles for compute_103)
__device__ __forceinline__ void mma16816(float (&d)[4], const uint32_t (&a)[4],
                                         const uint32_t (&b)[2]) {
    asm volatile("mma.sync.aligned.m16n8k16.row.col.f32.bf16.bf16.f32 "
                 "{%0,%1,%2,%3}, {%4,%5,%6,%7}, {%8,%9}, {%0,%1,%2,%3};"
                 : "+f"(d[0]), "+f"(d[1]), "+f"(d[2]), "+f"(d[3])
                 : "r"(a[0]), "r"(a[1]), "r"(a[2]), "r"(a[3]), "r"(b[0]), "r"(b[1]));
}

// cp.async helpers (sm_80+ PTX)
__device__ __forceinline__ void cpa16(uint32_t saddr, const void* g) {
    asm volatile("cp.async.cg.shared.global [%0], [%1], 16;" :: "r"(saddr), "l"(g));
}
#define CPA_COMMIT() asm volatile("cp.async.commit_group;")
#define CPA_WAIT0()  asm volatile("cp.async.wait_group 0;")

// ---------------- prep: fold weights (fp32 + hi/lo bf16) + init pool ----------------
__device__ __forceinline__ float weff_val(const float* __restrict__ W, int O, int C, int i) {
    int j = i / C, c = i - j * C;
    if (j < O) return W[(size_t)j * 2 * C + c];
    int jo = j - O;
    return W[(size_t)jo * 2 * C + C + c] - W[(size_t)jo * 2 * C + c];
}
__global__ void prep_kernel(const float* __restrict__ w1, const float* __restrict__ w2,
                            const float* __restrict__ w3, const float* __restrict__ w4) {
    int i = blockIdx.x * 256 + threadIdx.x;
    if (i < Bsz * 1024) g_pool[i] = 0u;
    if (i >= WEND) return;
    float v;
    if (i < WOFF2)      v = weff_val(w1, 64, 3, i - WOFF1);
    else if (i < WOFF3) v = weff_val(w2, 64, 64, i - WOFF2);
    else if (i < WOFF4) v = weff_val(w3, 128, 64, i - WOFF3);
    else                v = weff_val(w4, 256, 128, i - WOFF4);
    g_Weff[i] = v;
    __nv_bfloat16 h = __float2bfloat16(v);
    g_Wh[i] = h;
    g_Wl[i] = __float2bfloat16(v - __bfloat162float(h));
}

__global__ void sqnorm1_kernel(const float* __restrict__ x) {
    int i = blockIdx.x * 256 + threadIdx.x;
    if (i >= Bsz * Npt) return;
    const float* p = x + (size_t)i * 3;
    g_xx[i] = p[0] * p[0] + p[1] * p[1] + p[2] * p[2];
}

// ---------------- layer-1 fp32 GEMM (K=3): DIST(SYRK) and FEAT ----------------
template <bool DIST>
__global__ void __launch_bounds__(256, 2)
gemm128_kernel(const float* __restrict__ Aext, int Boff, int Csel, int ldc, long sC) {
    constexpr int KDIM = 3;
    __shared__ float As[16][132];
    __shared__ float Bs[16][132];

    const int tid = threadIdx.x;
    const int tx = tid & 15, ty = tid >> 4;
    const int z = blockIdx.z;
    const int lda = 3;

    int bx, by;
    if (DIST) {
        int t = blockIdx.x;
        bx = 0;
        while (t >= bx + 1) { t -= bx + 1; bx++; }
        by = t;
    } else {
        bx = blockIdx.x; by = blockIdx.y;
    }
    const int row0 = bx * 128;
    const int col0 = by * 128;

    const float* A = Aext + (size_t)z * (DIST ? 3 * Npt : 0);
    const float* Bt;
    int ldbb;
    if (DIST) { Bt = A; ldbb = lda; }
    else      { Bt = g_Weff + Boff; ldbb = KDIM; }

    float acc[8][8];
#pragma unroll
    for (int i = 0; i < 8; i++)
#pragma unroll
        for (int j = 0; j < 8; j++) acc[i][j] = 0.f;

#pragma unroll
    for (int l = 0; l < 8; l++) {
        int i = tid + l * 256;
        int r = i >> 4, k = i & 15;
        As[k][r] = (k < KDIM) ? A[(size_t)(row0 + r) * lda + k] : 0.f;
        Bs[k][r] = (k < KDIM) ? Bt[(size_t)(col0 + r) * ldbb + k] : 0.f;
    }
    __syncthreads();
#pragma unroll
    for (int k = 0; k < 3; k++) {
        float4 a0 = *(const float4*)&As[k][ty * 4];
        float4 a1 = *(const float4*)&As[k][ty * 4 + 64];
        float4 b0 = *(const float4*)&Bs[k][tx * 4];
        float4 b1 = *(const float4*)&Bs[k][tx * 4 + 64];
        float av[8] = {a0.x, a0.y, a0.z, a0.w, a1.x, a1.y, a1.z, a1.w};
        float bv[8] = {b0.x, b0.y, b0.z, b0.w, b1.x, b1.y, b1.z, b1.w};
#pragma unroll
        for (int i = 0; i < 8; i++)
#pragma unroll
            for (int j = 0; j < 8; j++)
                acc[i][j] = fmaf(av[i], bv[j], acc[i][j]);
    }

    float* Cp = ((Csel == 0) ? g_dist : g_Y) + (size_t)z * sC;

    if (DIST) {
        const float* xx = g_xx + (size_t)z * Npt;
        float xr[8], xc8[8];
#pragma unroll
        for (int i = 0; i < 8; i++) {
            xr[i]  = xx[row0 + (i >> 2) * 64 + ty * 4 + (i & 3)];
            xc8[i] = xx[col0 + (i >> 2) * 64 + tx * 4 + (i & 3)];
        }
#pragma unroll
        for (int i = 0; i < 8; i++) {
            int r = row0 + (i >> 2) * 64 + ty * 4 + (i & 3);
#pragma unroll
            for (int cs = 0; cs < 2; cs++) {
                float4 o;
                o.x = 2.f * acc[i][cs * 4 + 0] - xr[i] - xc8[cs * 4 + 0];
                o.y = 2.f * acc[i][cs * 4 + 1] - xr[i] - xc8[cs * 4 + 1];
                o.z = 2.f * acc[i][cs * 4 + 2] - xr[i] - xc8[cs * 4 + 2];
                o.w = 2.f * acc[i][cs * 4 + 3] - xr[i] - xc8[cs * 4 + 3];
                *(float4*)&Cp[(size_t)r * ldc + col0 + cs * 64 + tx * 4] = o;
            }
        }
        if (bx != by) {
#pragma unroll
            for (int j = 0; j < 8; j++) {
                int c = col0 + (j >> 2) * 64 + tx * 4 + (j & 3);
#pragma unroll
                for (int rs = 0; rs < 2; rs++) {
                    float4 o;
                    o.x = 2.f * acc[rs * 4 + 0][j] - xr[rs * 4 + 0] - xc8[j];
                    o.y = 2.f * acc[rs * 4 + 1][j] - xr[rs * 4 + 1] - xc8[j];
                    o.z = 2.f * acc[rs * 4 + 2][j] - xr[rs * 4 + 2] - xc8[j];
                    o.w = 2.f * acc[rs * 4 + 3][j] - xr[rs * 4 + 3] - xc8[j];
                    *(float4*)&Cp[(size_t)c * ldc + row0 + rs * 64 + ty * 4] = o;
                }
            }
        }
    } else {
#pragma unroll
        for (int i = 0; i < 8; i++) {
            int r = row0 + (i >> 2) * 64 + ty * 4 + (i & 3);
#pragma unroll
            for (int cs = 0; cs < 2; cs++) {
                float4 o;
                o.x = acc[i][cs * 4 + 0];
                o.y = acc[i][cs * 4 + 1];
                o.z = acc[i][cs * 4 + 2];
                o.w = acc[i][cs * 4 + 3];
                *(float4*)&Cp[(size_t)r * ldc + col0 + cs * 64 + tx * 4] = o;
            }
        }
    }
}

// ---------------- unified bf16-split mma GEMM (layers 2-4) ----------------
// cp.async double-buffered, occupancy 2, one __syncthreads per K-chunk.
template <int KCHUNKS, bool DIST>
__global__ void __launch_bounds__(256, 2)
mma_gemm_kernel(int chanoff, int woff, int twoO) {
    __shared__ __nv_bfloat16 sAh[2][128 * CKS];
    __shared__ __nv_bfloat16 sAl[2][128 * CKS];
    __shared__ __nv_bfloat16 sBh[2][128 * CKS];
    __shared__ __nv_bfloat16 sBl[2][128 * CKS];

    const int tid = threadIdx.x;
    const int wid = tid >> 5, lane = tid & 31;
    const int warp_m = wid & 3, warp_n = wid >> 2;
    const int lr = tid >> 1, lkb = (tid & 1) * 8;
    const int grp = lane >> 2, kq = (lane & 3) * 2;
    const int soffB = (lr * CKS + lkb) * 2;   // bytes

    size_t aoff, boff;
    const __nv_bfloat16 *Bh_, *Bl_;
    if (DIST) {
        aoff = (size_t)(blockIdx.z * 1024 + blockIdx.x * 128 + lr) * 512 + chanoff + lkb;
        boff = (size_t)(blockIdx.z * 1024 + blockIdx.y * 128 + lr) * 512 + chanoff + lkb;
        Bh_ = g_Fh; Bl_ = g_Fl;
    } else {
        aoff = (size_t)(blockIdx.x * 128 + lr) * 512 + chanoff + lkb;
        boff = (size_t)(blockIdx.y * 128 + lr) * (KCHUNKS * 16) + lkb;
        Bh_ = g_Wh + woff; Bl_ = g_Wl + woff;
    }

    const uint32_t sah = (uint32_t)__cvta_generic_to_shared(sAh[0]) + soffB;
    const uint32_t sal = (uint32_t)__cvta_generic_to_shared(sAl[0]) + soffB;
    const uint32_t sbh = (uint32_t)__cvta_generic_to_shared(sBh[0]) + soffB;
    const uint32_t sbl = (uint32_t)__cvta_generic_to_shared(sBl[0]) + soffB;

    float acc[2][8][4];
#pragma unroll
    for (int mt = 0; mt < 2; mt++)
#pragma unroll
        for (int nt = 0; nt < 8; nt++)
#pragma unroll
            for (int f = 0; f < 4; f++) acc[mt][nt][f] = 0.f;

    // issue chunk 0 into buf 0
    cpa16(sah, &g_Fh[aoff]);
    cpa16(sal, &g_Fl[aoff]);
    cpa16(sbh, &Bh_[boff]);
    cpa16(sbl, &Bl_[boff]);
    CPA_COMMIT();
    CPA_WAIT0();
    __syncthreads();

#pragma unroll
    for (int ch = 0; ch < KCHUNKS; ch++) {
        const int buf = ch & 1;
        if (ch + 1 < KCHUNKS) {
            const int nb = (ch + 1) & 1;
            const int kk = (ch + 1) * 16;
            cpa16(sah + nb * BUFB, &g_Fh[aoff + kk]);
            cpa16(sal + nb * BUFB, &g_Fl[aoff + kk]);
            cpa16(sbh + nb * BUFB, &Bh_[boff + kk]);
            cpa16(sbl + nb * BUFB, &Bl_[boff + kk]);
            CPA_COMMIT();
        }
        uint32_t ah[2][4], al[2][4], bh[8][2], bl[8][2];
#pragma unroll
        for (int mt = 0; mt < 2; mt++) {
            int r0 = (warp_m * 32 + mt * 16 + grp) * CKS;
            ah[mt][0] = *(const uint32_t*)&sAh[buf][r0 + kq];
            ah[mt][1] = *(const uint32_t*)&sAh[buf][r0 + 8 * CKS + kq];
            ah[mt][2] = *(const uint32_t*)&sAh[buf][r0 + kq + 8];
            ah[mt][3] = *(const uint32_t*)&sAh[buf][r0 + 8 * CKS + kq + 8];
            al[mt][0] = *(const uint32_t*)&sAl[buf][r0 + kq];
            al[mt][1] = *(const uint32_t*)&sAl[buf][r0 + 8 * CKS + kq];
            al[mt][2] = *(const uint32_t*)&sAl[buf][r0 + kq + 8];
            al[mt][3] = *(const uint32_t*)&sAl[buf][r0 + 8 * CKS + kq + 8];
        }
#pragma unroll
        for (int nt = 0; nt < 8; nt++) {
            int n0 = (warp_n * 64 + nt * 8 + grp) * CKS;
            bh[nt][0] = *(const uint32_t*)&sBh[buf][n0 + kq];
            bh[nt][1] = *(const uint32_t*)&sBh[buf][n0 + kq + 8];
            bl[nt][0] = *(const uint32_t*)&sBl[buf][n0 + kq];
            bl[nt][1] = *(const uint32_t*)&sBl[buf][n0 + kq + 8];
        }
#pragma unroll
        for (int mt = 0; mt < 2; mt++)
#pragma unroll
            for (int nt = 0; nt < 8; nt++) {
                mma16816(acc[mt][nt], ah[mt], bh[nt]);
                mma16816(acc[mt][nt], ah[mt], bl[nt]);
                mma16816(acc[mt][nt], al[mt], bh[nt]);
            }
        if (ch + 1 < KCHUNKS) {
            CPA_WAIT0();
            __syncthreads();
        }
    }

    if (DIST) {
        const float* xx = g_xx + (size_t)blockIdx.z * Npt;
        float* Cp = g_dist + (size_t)blockIdx.z * Npt * Npt;
        const int rb = blockIdx.x * 128 + warp_m * 32;
        const int cb = blockIdx.y * 128 + warp_n * 64;
        float xr[2][2];
#pragma unroll
        for (int mt = 0; mt < 2; mt++) {
            xr[mt][0] = xx[rb + mt * 16 + grp];
            xr[mt][1] = xx[rb + mt * 16 + grp + 8];
        }
#pragma unroll
        for (int nt = 0; nt < 8; nt++) {
            int c = cb + nt * 8 + kq;
            float xc0 = xx[c], xc1 = xx[c + 1];
#pragma unroll
            for (int mt = 0; mt < 2; mt++) {
                int r = rb + mt * 16 + grp;
                *(float2*)&Cp[(size_t)r * Npt + c] = make_float2(
                    2.f * acc[mt][nt][0] - xr[mt][0] - xc0,
                    2.f * acc[mt][nt][1] - xr[mt][0] - xc1);
                *(float2*)&Cp[(size_t)(r + 8) * Npt + c] = make_float2(
                    2.f * acc[mt][nt][2] - xr[mt][1] - xc0,
                    2.f * acc[mt][nt][3] - xr[mt][1] - xc1);
            }
        }
    } else {
        const int rb = blockIdx.x * 128 + warp_m * 32;
        const int cb = blockIdx.y * 128 + warp_n * 64;
#pragma unroll
        for (int mt = 0; mt < 2; mt++) {
            int r = rb + mt * 16 + grp;
#pragma unroll
            for (int nt = 0; nt < 8; nt++) {
                int c = cb + nt * 8 + kq;
                *(float2*)&g_Y[(size_t)r * twoO + c] =
                    make_float2(acc[mt][nt][0], acc[mt][nt][1]);
                *(float2*)&g_Y[(size_t)(r + 8) * twoO + c] =
                    make_float2(acc[mt][nt][2], acc[mt][nt][3]);
            }
        }
    }
}

// ---------------- top-K (K=20): warp/row, REDUX select + 2-level rescan ----------------
__global__ void topk_kernel() {
    int row = (blockIdx.x << 3) + (threadIdx.x >> 5);
    int lane = threadIdx.x & 31;
    const float* rp = g_dist + (size_t)row * Npt + lane;
    float v[32];
#pragma unroll
    for (int j = 0; j < 32; j++) v[j] = rp[j * 32];
    float gm[4];
    int gj[4];
#pragma unroll
    for (int g = 0; g < 4; g++) {
        gm[g] = v[g * 8]; gj[g] = g * 8;
#pragma unroll
        for (int j = 1; j < 8; j++)
            if (v[g * 8 + j] > gm[g]) { gm[g] = v[g * 8 + j]; gj[g] = g * 8 + j; }
    }
    float lm = gm[0];
    int li = gj[0];
#pragma unroll
    for (int g = 1; g < 4; g++)
        if (gm[g] > lm) { lm = gm[g]; li = gj[g]; }
    int gi = li * 32 + lane;

    for (int k = 0; k < KNN; k++) {
        unsigned mykey = fenc(lm);
        unsigned wmax = __reduce_max_sync(0xffffffffu, mykey);
        unsigned cand = (mykey == wmax) ? (unsigned)gi : 0xFFFFFFFFu;
        unsigned wini = __reduce_min_sync(0xffffffffu, cand);
        if (lane == 0) g_idx[row * KNN + k] = (int)wini;
        if (mykey == wmax && gi == (int)wini) {
            int jr = li, gr = li >> 3;
#pragma unroll
            for (int g = 0; g < 4; g++)
                if (g == gr) {
#pragma unroll
                    for (int j = 0; j < 8; j++)
                        if (g * 8 + j == jr) v[g * 8 + j] = -FLT_MAX;
                    gm[g] = v[g * 8]; gj[g] = g * 8;
#pragma unroll
                    for (int j = 1; j < 8; j++)
                        if (v[g * 8 + j] > gm[g]) { gm[g] = v[g * 8 + j]; gj[g] = g * 8 + j; }
                }
            lm = gm[0]; li = gj[0];
#pragma unroll
            for (int g = 1; g < 4; g++)
                if (gm[g] > lm) { lm = gm[g]; li = gj[g]; }
            gi = li * 32 + lane;
        }
    }
}

// ---- gather + bias + bn + lrelu + max over K; emit bf16 hi/lo features + sqnorm ----
__global__ void aggregate_kernel(int O, const float* __restrict__ bias,
                                 const float* __restrict__ bng, const float* __restrict__ bnb,
                                 int outoff) {
    int bn = blockIdx.x;
    int b = bn >> 10;
    int o = threadIdx.x;
    __shared__ int sidx[KNN];
    __shared__ float sp[8];
    if (o < KNN) sidx[o] = g_idx[bn * KNN + o];
    __syncthreads();
    int twoO = 2 * O;
    const float* Yrow = g_Y + (size_t)bn * twoO;
    float ctr = Yrow[O + o];
    if (bias) ctr += bias[o];
    float scale = bng[o] * rsqrtf(1.0f + 1e-5f);
    float shift = bnb[o];
    const float* Yb = g_Y + (size_t)(b << 10) * twoO;
    float m = -FLT_MAX;
#pragma unroll
    for (int k = 0; k < KNN; k++) {
        float v = Yb[(size_t)sidx[k] * twoO + o] + ctr;
        v = fmaf(v, scale, shift);
        v = (v >= 0.f) ? v : 0.01f * v;
        m = fmaxf(m, v);
    }
    __nv_bfloat16 h = __float2bfloat16(m);
    g_Fh[(size_t)bn * 512 + outoff + o] = h;
    g_Fl[(size_t)bn * 512 + outoff + o] = __float2bfloat16(m - __bfloat162float(h));
    float s = m * m;
#pragma unroll
    for (int off = 16; off; off >>= 1) s += __shfl_xor_sync(0xffffffffu, s, off);
    if ((o & 31) == 0) sp[o >> 5] = s;
    __syncthreads();
    if (o == 0) {
        float t = 0.f;
        int nw = O >> 5;
        for (int w = 0; w < nw; w++) t += sp[w];
        g_xx[bn] = t;
    }
}

// ---------------- conv5 weight split ----------------
__global__ void cvtB_kernel(const float* __restrict__ w5) {
    int i = blockIdx.x * 256 + threadIdx.x;          // [0, 1024*512)
    float x = w5[i];
    __nv_bfloat16 h = __float2bfloat16(x);
    g_Bh[i] = h;
    g_Bl[i] = __float2bfloat16(x - __bfloat162float(h));
}

// ------- conv5: bf16-split mma GEMM, SPLIT-K (2 phases of 256 channels) -------
// PHASE 0: K = [0,256)   -> writes partial C to g_C5 (runs early, overlapped)
// PHASE 1: K = [256,512) -> adds g_C5, fused max-pool epilogue
template <int PHASE>
__global__ void __launch_bounds__(256, 2) conv5_mma_kernel() {
    __shared__ __nv_bfloat16 sAh[2][128 * CKS];
    __shared__ __nv_bfloat16 sAl[2][128 * CKS];
    __shared__ __nv_bfloat16 sBh[2][128 * CKS];
    __shared__ __nv_bfloat16 sBl[2][128 * CKS];

    const int tid = threadIdx.x;
    const int wid = tid >> 5, lane = tid & 31;
    const int warp_m = wid & 3, warp_n = wid >> 2;
    const int row0 = blockIdx.x * 128;
    const int col0 = blockIdx.y * 128;
    const int batch = row0 >> 10;
    const int koff = PHASE * 256;

    const int lr = tid >> 1;
    const int lkb = (tid & 1) * 8;
    const size_t aoff = (size_t)(row0 + lr) * 512 + koff + lkb;
    const size_t boff = (size_t)(col0 + lr) * 512 + koff + lkb;
    const int soffB = (lr * CKS + lkb) * 2;

    const uint32_t sah = (uint32_t)__cvta_generic_to_shared(sAh[0]) + soffB;
    const uint32_t sal = (uint32_t)__cvta_generic_to_shared(sAl[0]) + soffB;
    const uint32_t sbh = (uint32_t)__cvta_generic_to_shared(sBh[0]) + soffB;
    const uint32_t sbl = (uint32_t)__cvta_generic_to_shared(sBl[0]) + soffB;

    float acc[2][8][4];
#pragma unroll
    for (int mt = 0; mt < 2; mt++)
#pragma unroll
        for (int nt = 0; nt < 8; nt++)
#pragma unroll
            for (int f = 0; f < 4; f++) acc[mt][nt][f] = 0.f;

    cpa16(sah, &g_Fh[aoff]);
    cpa16(sal, &g_Fl[aoff]);
    cpa16(sbh, &g_Bh[boff]);
    cpa16(sbl, &g_Bl[boff]);
    CPA_COMMIT();
    CPA_WAIT0();
    __syncthreads();

    const int grp = lane >> 2;
    const int kq = (lane & 3) * 2;

    for (int ch = 0; ch < 16; ch++) {
        const int buf = ch & 1;
        if (ch < 15) {
            const int nb = (ch + 1) & 1;
            const int kk = (ch + 1) * 16;
            cpa16(sah + nb * BUFB, &g_Fh[aoff + kk]);
            cpa16(sal + nb * BUFB, &g_Fl[aoff + kk]);
            cpa16(sbh + nb * BUFB, &g_Bh[boff + kk]);
            cpa16(sbl + nb * BUFB, &g_Bl[boff + kk]);
            CPA_COMMIT();
        }
        uint32_t ah[2][4], al[2][4], bh[8][2], bl[8][2];
#pragma unroll
        for (int mt = 0; mt < 2; mt++) {
            int r0 = (warp_m * 32 + mt * 16 + grp) * CKS;
            ah[mt][0] = *(const uint32_t*)&sAh[buf][r0 + kq];
            ah[mt][1] = *(const uint32_t*)&sAh[buf][r0 + 8 * CKS + kq];
            ah[mt][2] = *(const uint32_t*)&sAh[buf][r0 + kq + 8];
            ah[mt][3] = *(const uint32_t*)&sAh[buf][r0 + 8 * CKS + kq + 8];
            al[mt][0] = *(const uint32_t*)&sAl[buf][r0 + kq];
            al[mt][1] = *(const uint32_t*)&sAl[buf][r0 + 8 * CKS + kq];
            al[mt][2] = *(const uint32_t*)&sAl[buf][r0 + kq + 8];
            al[mt][3] = *(const uint32_t*)&sAl[buf][r0 + 8 * CKS + kq + 8];
        }
#pragma unroll
        for (int nt = 0; nt < 8; nt++) {
            int n0 = (warp_n * 64 + nt * 8 + grp) * CKS;
            bh[nt][0] = *(const uint32_t*)&sBh[buf][n0 + kq];
            bh[nt][1] = *(const uint32_t*)&sBh[buf][n0 + kq + 8];
            bl[nt][0] = *(const uint32_t*)&sBl[buf][n0 + kq];
            bl[nt][1] = *(const uint32_t*)&sBl[buf][n0 + kq + 8];
        }
#pragma unroll
        for (int mt = 0; mt < 2; mt++)
#pragma unroll
            for (int nt = 0; nt < 8; nt++) {
                mma16816(acc[mt][nt], ah[mt], bh[nt]);
                mma16816(acc[mt][nt], ah[mt], bl[nt]);
                mma16816(acc[mt][nt], al[mt], bh[nt]);
            }
        if (ch < 15) {
            CPA_WAIT0();
            __syncthreads();
        }
    }

    const int rbase = row0 + warp_m * 32;
    const int cbase = col0 + warp_n * 64;

    if (PHASE == 0) {
        // store partial C
#pragma unroll
        for (int mt = 0; mt < 2; mt++) {
            int r = rbase + mt * 16 + grp;
#pragma unroll
            for (int nt = 0; nt < 8; nt++) {
                int c = cbase + nt * 8 + kq;
                *(float2*)&g_C5[(size_t)r * 1024 + c] =
                    make_float2(acc[mt][nt][0], acc[mt][nt][1]);
                *(float2*)&g_C5[(size_t)(r + 8) * 1024 + c] =
                    make_float2(acc[mt][nt][2], acc[mt][nt][3]);
            }
        }
        return;
    }

    // PHASE 1: add partial C, then fused max-pool epilogue
#pragma unroll
    for (int mt = 0; mt < 2; mt++) {
        int r = rbase + mt * 16 + grp;
#pragma unroll
        for (int nt = 0; nt < 8; nt++) {
            int c = cbase + nt * 8 + kq;
            float2 p0 = *(const float2*)&g_C5[(size_t)r * 1024 + c];
            float2 p1 = *(const float2*)&g_C5[(size_t)(r + 8) * 1024 + c];
            acc[mt][nt][0] += p0.x;
            acc[mt][nt][1] += p0.y;
            acc[mt][nt][2] += p1.x;
            acc[mt][nt][3] += p1.y;
        }
    }

    float cmax[8][2];
#pragma unroll
    for (int nt = 0; nt < 8; nt++) {
        cmax[nt][0] = fmaxf(fmaxf(acc[0][nt][0], acc[0][nt][2]),
                            fmaxf(acc[1][nt][0], acc[1][nt][2]));
        cmax[nt][1] = fmaxf(fmaxf(acc[0][nt][1], acc[0][nt][3]),
                            fmaxf(acc[1][nt][1], acc[1][nt][3]));
    }
#pragma unroll
    for (int off = 16; off >= 4; off >>= 1)
#pragma unroll
        for (int nt = 0; nt < 8; nt++) {
            cmax[nt][0] = fmaxf(cmax[nt][0], __shfl_xor_sync(0xffffffffu, cmax[nt][0], off));
            cmax[nt][1] = fmaxf(cmax[nt][1], __shfl_xor_sync(0xffffffffu, cmax[nt][1], off));
        }
    if (lane < 4) {
        unsigned* pp = &g_pool[batch * 1024 + col0 + warp_n * 64];
#pragma unroll
        for (int nt = 0; nt < 8; nt++) {
            atomicMax(&pp[nt * 8 + lane * 2], fenc(cmax[nt][0]));
            atomicMax(&pp[nt * 8 + lane * 2 + 1], fenc(cmax[nt][1]));
        }
    }
}

// ---------------- fused MLP head ----------------
__global__ void mlp_kernel(const float* __restrict__ lin1_w,
                           const float* __restrict__ bn6_g, const float* __restrict__ bn6_b,
                           const float* __restrict__ lin2_w, const float* __restrict__ lin2_b,
                           const float* __restrict__ bn7_g, const float* __restrict__ bn7_b,
                           const float* __restrict__ lin3_w, const float* __restrict__ lin3_b,
                           float* __restrict__ out) {
    int b = blockIdx.x, t = threadIdx.x;
    __shared__ float sy[1024];
    __shared__ float s1[512];
    __shared__ float s2s[256];
    for (int i = t; i < 1024; i += 256) sy[i] = fdec(g_pool[b * 1024 + i]);
    __syncthreads();
    const float r = rsqrtf(1.0f + 1e-5f);
    for (int j = t; j < 512; j += 256) {
        const float* w = lin1_w + (size_t)j * 1024;
        float acc = 0.f;
        for (int c = 0; c < 1024; c++) acc = fmaf(w[c], sy[c], acc);
        float v = fmaf(acc, bn6_g[j] * r, bn6_b[j]);
        s1[j] = (v >= 0.f) ? v : 0.01f * v;
    }
    __syncthreads();
    {
        const float* w = lin2_w + (size_t)t * 512;
        float acc = lin2_b[t];
        for (int c = 0; c < 512; c++) acc = fmaf(w[c], s1[c], acc);
        float v = fmaf(acc, bn7_g[t] * r, bn7_b[t]);
        s2s[t] = (v >= 0.f) ? v : 0.01f * v;
    }
    __syncthreads();
    if (t < 40) {
        const float* w = lin3_w + (size_t)t * 256;
        float acc = lin3_b[t];
        for (int c = 0; c < 256; c++) acc = fmaf(w[c], s2s[c], acc);
        out[b * 40 + t] = acc;
    }
}

// ---------------- stream/event lazy init (host-side objects only) ----------------
static cudaStream_t s2 = nullptr;
static cudaEvent_t evFork[4], evJoin[4], evC5;
static bool s_init = false;
static void ensure_streams() {
    if (s_init) return;
    cudaStreamCreateWithFlags(&s2, cudaStreamNonBlocking);
    for (int i = 0; i < 4; i++) {
        cudaEventCreateWithFlags(&evFork[i], cudaEventDisableTiming);
        cudaEventCreateWithFlags(&evJoin[i], cudaEventDisableTiming);
    }
    cudaEventCreateWithFlags(&evC5, cudaEventDisableTiming);
    s_init = true;
}

extern "C" void kernel_launch(void* const* d_in, const int* in_sizes, int n_in,
                              void* d_out, int out_size) {
    const float* x       = (const float*)d_in[0];
    const float* conv1_w = (const float*)d_in[1];
    const float* conv1_b = (const float*)d_in[2];
    const float* bn1_g   = (const float*)d_in[3];
    const float* bn1_b   = (const float*)d_in[4];
    const float* conv2_w = (const float*)d_in[5];
    const float* bn2_g   = (const float*)d_in[6];
    const float* bn2_b   = (const float*)d_in[7];
    const float* conv3_w = (const float*)d_in[8];
    const float* bn3_g   = (const float*)d_in[9];
    const float* bn3_b   = (const float*)d_in[10];
    const float* conv4_w = (const float*)d_in[11];
    const float* bn4_g   = (const float*)d_in[12];
    const float* bn4_b   = (const float*)d_in[13];
    const float* conv5_w = (const float*)d_in[14];
    const float* lin1_w  = (const float*)d_in[15];
    const float* bn6_g   = (const float*)d_in[16];
    const float* bn6_b   = (const float*)d_in[17];
    const float* lin2_w  = (const float*)d_in[18];
    const float* lin2_b  = (const float*)d_in[19];
    const float* bn7_g   = (const float*)d_in[20];
    const float* bn7_b   = (const float*)d_in[21];
    const float* lin3_w  = (const float*)d_in[22];
    const float* lin3_b  = (const float*)d_in[23];
    float* out = (float*)d_out;

    ensure_streams();

    // prep on main stream (everything depends on it)
    prep_kernel<<<(WEND + 255) / 256, 256>>>(conv1_w, conv2_w, conv3_w, conv4_w);
    cvtB_kernel<<<1024 * 512 / 256, 256>>>(conv5_w);
    sqnorm1_kernel<<<32, 256>>>(x);

    const long sDist = (long)Npt * Npt;

    // ----- layer 1 (C=3, O=64): fp32 path; feat ∥ (dist, topk) -----
    cudaEventRecord(evFork[0], 0);
    cudaStreamWaitEvent(s2, evFork[0], 0);
    gemm128_kernel<false><<<dim3(64, 1, 1), 256, 0, s2>>>(x, WOFF1, 1, 128, 0);
    cudaEventRecord(evJoin[0], s2);
    gemm128_kernel<true><<<dim3(36, 1, Bsz), 256>>>(x, 0, 0, Npt, sDist);
    topk_kernel<<<Bsz * Npt / 8, 256>>>();
    cudaStreamWaitEvent(0, evJoin[0], 0);
    aggregate_kernel<<<Bsz * Npt, 64>>>(64, conv1_b, bn1_g, bn1_b, 0);

    // ----- layer 2 (C=64, O=64): feat ∥ (dist, topk) -----
    cudaEventRecord(evFork[1], 0);
    cudaStreamWaitEvent(s2, evFork[1], 0);
    mma_gemm_kernel<4, false><<<dim3(64, 1), 256, 0, s2>>>(0, WOFF2, 128);
    cudaEventRecord(evJoin[1], s2);
    mma_gemm_kernel<4, true><<<dim3(8, 8, Bsz), 256>>>(0, 0, 0);
    topk_kernel<<<Bsz * Npt / 8, 256>>>();
    cudaStreamWaitEvent(0, evJoin[1], 0);
    aggregate_kernel<<<Bsz * Npt, 64>>>(64, nullptr, bn2_g, bn2_b, 64);

    // ----- layer 3 (C=64, O=128) -----
    cudaEventRecord(evFork[2], 0);
    cudaStreamWaitEvent(s2, evFork[2], 0);
    mma_gemm_kernel<4, false><<<dim3(64, 2), 256, 0, s2>>>(64, WOFF3, 256);
    cudaEventRecord(evJoin[2], s2);
    mma_gemm_kernel<4, true><<<dim3(8, 8, Bsz), 256>>>(64, 0, 0);
    topk_kernel<<<Bsz * Npt / 8, 256>>>();
    cudaStreamWaitEvent(0, evJoin[2], 0);
    aggregate_kernel<<<Bsz * Npt, 128>>>(128, nullptr, bn3_g, bn3_b, 128);

    // ----- layer 4 (C=128, O=256): feat + conv5-phase0 ∥ (dist, topk) -----
    cudaEventRecord(evFork[3], 0);
    cudaStreamWaitEvent(s2, evFork[3], 0);
    mma_gemm_kernel<8, false><<<dim3(64, 4), 256, 0, s2>>>(128, WOFF4, 512);
    cudaEventRecord(evJoin[3], s2);
    conv5_mma_kernel<0><<<dim3(64, 8), 256, 0, s2>>>();   // K=[0,256): x1|x2|x3 only
    cudaEventRecord(evC5, s2);
    mma_gemm_kernel<8, true><<<dim3(8, 8, Bsz), 256>>>(128, 0, 0);
    topk_kernel<<<Bsz * Npt / 8, 256>>>();
    cudaStreamWaitEvent(0, evJoin[3], 0);
    aggregate_kernel<<<Bsz * Npt, 256>>>(256, nullptr, bn4_g, bn4_b, 256);

    // ----- conv5 phase 1 (K=[256,512)) + partial add + fused global max-pool -----
    cudaStreamWaitEvent(0, evC5, 0);
    conv5_mma_kernel<1><<<dim3(64, 8), 256>>>();

    // ----- MLP head -----
    mlp_kernel<<<Bsz, 256>>>(lin1_w, bn6_g, bn6_b, lin2_w, lin2_b,
                             bn7_g, bn7_b, lin3_w, lin3_b, out);
}